// round 11
// baseline (speedup 1.0000x reference)
#include <cuda_runtime.h>
#include <cuda_bf16.h>
#include <stdint.h>
#include <math.h>

// Problem constants
#define T_DIM 1024
#define B_DIM 8
#define D_DIM 1024
#define H_DIM 16
#define HD_DIM 64
#define M_ROWS (T_DIM * B_DIM)        // 8192

// Scratch (no cudaMalloc allowed)
#define PLANE_ELEMS (128 * 1024 * 64)
__device__ __nv_bfloat16 g_qh[PLANE_ELEMS], g_ql[PLANE_ELEMS];   // head planes
__device__ __nv_bfloat16 g_kh[PLANE_ELEMS], g_kl[PLANE_ELEMS];
__device__ __nv_bfloat16 g_vh[PLANE_ELEMS], g_vl[PLANE_ELEMS];
__device__ __nv_bfloat16 g_xh[M_ROWS * D_DIM], g_xl[M_ROWS * D_DIM];  // input split
__device__ __nv_bfloat16 g_wh[D_DIM * D_DIM], g_wl[D_DIM * D_DIM];    // weight split
__device__ __nv_bfloat16 g_ch[M_ROWS * D_DIM], g_cl[M_ROWS * D_DIM];  // ctx split

// ===========================================================================
// Helpers
// ===========================================================================
__device__ __forceinline__ uint32_t smem_u32(const void* p) {
    uint32_t a;
    asm("{ .reg .u64 t; cvta.to.shared.u64 t, %1; cvt.u32.u64 %0, t; }"
        : "=r"(a) : "l"(p));
    return a;
}
#define SW128(o) ((o) ^ (((o) >> 3) & 0x70))

#define LDSM4(r, addr) \
    asm volatile("ldmatrix.sync.aligned.m8n8.x4.shared.b16 {%0,%1,%2,%3}, [%4];" \
        : "=r"((r)[0]), "=r"((r)[1]), "=r"((r)[2]), "=r"((r)[3]) : "r"(addr))

#define LDSM4T(r, addr) \
    asm volatile("ldmatrix.sync.aligned.m8n8.x4.trans.shared.b16 {%0,%1,%2,%3}, [%4];" \
        : "=r"((r)[0]), "=r"((r)[1]), "=r"((r)[2]), "=r"((r)[3]) : "r"(addr))

#define MMA_BF16(d, a, b0_, b1_) \
    asm volatile("mma.sync.aligned.m16n8k16.row.col.f32.bf16.bf16.f32 " \
        "{%0,%1,%2,%3}, {%4,%5,%6,%7}, {%8,%9}, {%0,%1,%2,%3};" \
        : "+f"((d)[0]), "+f"((d)[1]), "+f"((d)[2]), "+f"((d)[3]) \
        : "r"((a)[0]), "r"((a)[1]), "r"((a)[2]), "r"((a)[3]), \
          "r"(b0_), "r"(b1_))

__device__ __forceinline__ void sts128(uint32_t addr, uint32_t a, uint32_t b,
                                       uint32_t c, uint32_t d) {
    asm volatile("st.shared.v4.b32 [%0], {%1,%2,%3,%4};"
                 :: "r"(addr), "r"(a), "r"(b), "r"(c), "r"(d) : "memory");
}
// split fp32 pair -> (hi bf16x2 word, lo bf16x2 word)
__device__ __forceinline__ void cvt_pair(float f0, float f1,
                                         uint32_t& hw, uint32_t& lw) {
    __nv_bfloat162 h = __floats2bfloat162_rn(f0, f1);
    float g0 = __bfloat162float(__low2bfloat16(h));
    float g1 = __bfloat162float(__high2bfloat16(h));
    __nv_bfloat162 l = __floats2bfloat162_rn(f0 - g0, f1 - g1);
    hw = *reinterpret_cast<uint32_t*>(&h);
    lw = *reinterpret_cast<uint32_t*>(&l);
}

// ===========================================================================
// Preconvert: fp32 -> hi/lo bf16 planes
// ===========================================================================
__global__ __launch_bounds__(256) void cvt_kernel(
    const float* __restrict__ src, __nv_bfloat16* __restrict__ h,
    __nv_bfloat16* __restrict__ l, int n4) {
    int i = blockIdx.x * 256 + threadIdx.x;
    if (i < n4) {
        float4 v = ((const float4*)src)[i];
        uint32_t h0, h1, l0, l1;
        cvt_pair(v.x, v.y, h0, l0);
        cvt_pair(v.z, v.w, h1, l1);
        ((uint2*)h)[i] = make_uint2(h0, h1);
        ((uint2*)l)[i] = make_uint2(l0, l1);
    }
}

// ===========================================================================
// Split-bf16 warp-MMA GEMM v3: out = A[8192][1024] @ W^T + bias.
// A, W pre-split into hi/lo bf16 planes. cp.async 4-stage pipeline.
// Smem stage: A rows 0..127 (128B rows: [hi 32 bf16 | lo 32 bf16], SW128)
// at +0, W rows at +16384. Epilogues: fp32 C (Ph==nullptr) or scaled hi/lo
// bf16 head-major planes [b*16+h][t][64].
// ===========================================================================
#define NSTAGE 4
#define G_STAGE 32768
#define GEMM_SMEM (NSTAGE * G_STAGE)   // 131072

__global__ __launch_bounds__(256, 1) void gemm_tc_kernel(
    const __nv_bfloat16* __restrict__ Ah_, const __nv_bfloat16* __restrict__ Al_,
    const __nv_bfloat16* __restrict__ Wh_, const __nv_bfloat16* __restrict__ Wl_,
    const float* __restrict__ bias, float* __restrict__ C,
    __nv_bfloat16* __restrict__ Ph, __nv_bfloat16* __restrict__ Pl,
    float scale) {
    extern __shared__ char smem[];
    const uint32_t sb = smem_u32(smem);

    const int tid = threadIdx.x;
    const int wid = tid >> 5;
    const int lane = tid & 31;
    const int warp_m = wid >> 2;
    const int warp_n = wid & 3;
    const int row0 = blockIdx.y * 128;
    const int col0 = blockIdx.x * 128;

    const int grp = lane >> 3, rin = lane & 7;
    const int a_mrow = ((grp & 1) << 3) + rin;
    const int a_kb   = (grp >> 1) << 4;
    const int b_nrow = ((grp >> 1) << 3) + rin;
    const int b_kb   = (grp & 1) << 4;

    // cp.async chunk map: 8 chunks/thread/stage (4 A, 4 W)
    const __nv_bfloat16* gptr[8];
    uint32_t soff[8];
    #pragma unroll
    for (int j = 0; j < 8; j++) {
        int c = (j & 3) * 256 + tid;       // 0..1023
        int plane = c >> 9;                // 0 hi, 1 lo
        int r = (c >> 2) & 127;
        int seg = c & 3;
        if (j < 4) {
            gptr[j] = (plane ? Al_ : Ah_) + (size_t)(row0 + r) * 1024 + seg * 8;
            soff[j] = SW128(r * 128 + plane * 64 + seg * 16);
        } else {
            gptr[j] = (plane ? Wl_ : Wh_) + (size_t)(col0 + r) * 1024 + seg * 8;
            soff[j] = 16384 + SW128(r * 128 + plane * 64 + seg * 16);
        }
    }

    auto issue_stage = [&](int s) {
        const int kb = s * 32;
        const uint32_t dst = sb + (s & (NSTAGE - 1)) * G_STAGE;
        #pragma unroll
        for (int j = 0; j < 8; j++) {
            asm volatile("cp.async.cg.shared.global [%0], [%1], 16;"
                         :: "r"(dst + soff[j]), "l"(gptr[j] + kb));
        }
        asm volatile("cp.async.commit_group;" ::: "memory");
    };

    float acc[4][4][4];
    #pragma unroll
    for (int i = 0; i < 4; i++)
        #pragma unroll
        for (int j = 0; j < 4; j++)
            #pragma unroll
            for (int k = 0; k < 4; k++) acc[i][j][k] = 0.0f;

    // prologue: stages 0..NSTAGE-2
    #pragma unroll
    for (int p = 0; p < NSTAGE - 1; p++) issue_stage(p);

    #pragma unroll 1
    for (int s = 0; s < 32; s++) {
        asm volatile("cp.async.wait_group %0;" :: "n"(NSTAGE - 2) : "memory");
        __syncthreads();
        if (s + NSTAGE - 1 < 32) issue_stage(s + NSTAGE - 1);
        else asm volatile("cp.async.commit_group;" ::: "memory");

        const uint32_t AsB = sb + (s & (NSTAGE - 1)) * G_STAGE;
        const uint32_t BsB = AsB + 16384;
        #pragma unroll
        for (int ks = 0; ks < 2; ks++) {
            uint32_t ah[4][4], al[4][4], bh[2][4], bl[2][4];
            #pragma unroll
            for (int mt = 0; mt < 4; mt++) {
                int row = warp_m * 64 + mt * 16 + a_mrow;
                uint32_t off = row * 128 + ks * 32 + a_kb;
                LDSM4(ah[mt], AsB + SW128(off));
                LDSM4(al[mt], AsB + SW128(off + 64));
            }
            #pragma unroll
            for (int np = 0; np < 2; np++) {
                int row = warp_n * 32 + np * 16 + b_nrow;
                uint32_t off = row * 128 + ks * 32 + b_kb;
                LDSM4(bh[np], BsB + SW128(off));
                LDSM4(bl[np], BsB + SW128(off + 64));
            }
            #pragma unroll
            for (int mt = 0; mt < 4; mt++)
                #pragma unroll
                for (int np = 0; np < 2; np++)
                    #pragma unroll
                    for (int sub = 0; sub < 2; sub++) {
                        float* d = acc[mt][np * 2 + sub];
                        MMA_BF16(d, ah[mt], bh[np][sub * 2], bh[np][sub * 2 + 1]);
                        MMA_BF16(d, al[mt], bh[np][sub * 2], bh[np][sub * 2 + 1]);
                        MMA_BF16(d, ah[mt], bl[np][sub * 2], bl[np][sub * 2 + 1]);
                    }
        }
    }

    // Epilogue
    if (Ph == nullptr) {
        #pragma unroll
        for (int mt = 0; mt < 4; mt++) {
            int rg = row0 + warp_m * 64 + mt * 16 + (lane >> 2);
            #pragma unroll
            for (int nt = 0; nt < 4; nt++) {
                int cg = col0 + warp_n * 32 + nt * 8 + (lane & 3) * 2;
                float b0 = __ldg(&bias[cg]), b1 = __ldg(&bias[cg + 1]);
                float2 v0 = make_float2(acc[mt][nt][0] + b0, acc[mt][nt][1] + b1);
                float2 v1 = make_float2(acc[mt][nt][2] + b0, acc[mt][nt][3] + b1);
                *(float2*)&C[(size_t)rg * 1024 + cg] = v0;
                *(float2*)&C[(size_t)(rg + 8) * 1024 + cg] = v1;
            }
        }
    } else {
        #pragma unroll
        for (int mt = 0; mt < 4; mt++) {
            int rg = row0 + warp_m * 64 + mt * 16 + (lane >> 2);
            int t = rg >> 3, bb = rg & 7;
            #pragma unroll
            for (int nt = 0; nt < 4; nt++) {
                int cg = col0 + warp_n * 32 + nt * 8 + (lane & 3) * 2;
                int hh = cg >> 6, hd = cg & 63;
                size_t pb = ((size_t)(bb * 16 + hh)) * 65536 + (size_t)t * 64 + hd;
                float b0 = __ldg(&bias[cg]), b1 = __ldg(&bias[cg + 1]);
                uint32_t hw, lw;
                cvt_pair((acc[mt][nt][0] + b0) * scale,
                         (acc[mt][nt][1] + b1) * scale, hw, lw);
                *(uint32_t*)&Ph[pb] = hw;
                *(uint32_t*)&Pl[pb] = lw;
                cvt_pair((acc[mt][nt][2] + b0) * scale,
                         (acc[mt][nt][3] + b1) * scale, hw, lw);
                *(uint32_t*)&Ph[pb + 64] = hw;      // rg+8 -> t+1
                *(uint32_t*)&Pl[pb + 64] = lw;
            }
        }
    }
}

// ===========================================================================
// Tensor-core flash attention, split-bf16 3-term. CTA = 128 q-rows x 1 head.
// ctx written as hi/lo bf16 planes [t*8+b][1024] (feeds O-projection GEMM).
// ===========================================================================
#define ATTN_SMEM 98304   // 6 planes x 16 KB

__global__ __launch_bounds__(256, 1) void attn_tc_kernel(
    const __nv_bfloat16* __restrict__ qh, const __nv_bfloat16* __restrict__ ql,
    const __nv_bfloat16* __restrict__ kh, const __nv_bfloat16* __restrict__ kl,
    const __nv_bfloat16* __restrict__ vh, const __nv_bfloat16* __restrict__ vl,
    __nv_bfloat16* __restrict__ ch, __nv_bfloat16* __restrict__ cl) {
    extern __shared__ char smem[];
    const uint32_t sb = smem_u32(smem);
    const int tid = threadIdx.x, wid = tid >> 5, lane = tid & 31;
    const int grp = lane >> 3, rin = lane & 7;
    const int head = blockIdx.y;
    const int q0 = blockIdx.x * 128;
    const size_t hbase = (size_t)head * 65536;

    enum { QH = 0, QL = 16384, KH = 32768, KL = 49152, VH = 65536, VL = 81920 };

    {
        const uint4* sh = (const uint4*)(qh + hbase + (size_t)q0 * 64);
        const uint4* sl = (const uint4*)(ql + hbase + (size_t)q0 * 64);
        #pragma unroll
        for (int i = 0; i < 4; i++) {
            int c = tid + i * 256;
            uint32_t d = SW128(c * 16);
            uint4 a = sh[c]; sts128(sb + QH + d, a.x, a.y, a.z, a.w);
            uint4 b = sl[c]; sts128(sb + QL + d, b.x, b.y, b.z, b.w);
        }
    }
    __syncthreads();

    const int a_row = wid * 16 + ((grp & 1) << 3) + rin;
    const int a_kb = (grp >> 1) << 4;
    uint32_t qfh[4][4], qfl[4][4];
    #pragma unroll
    for (int ks = 0; ks < 4; ks++) {
        uint32_t off = a_row * 128 + ks * 32 + a_kb;
        LDSM4(qfh[ks], sb + QH + SW128(off));
        LDSM4(qfl[ks], sb + QL + SW128(off));
    }

    const int b_rowb = ((grp >> 1) << 3) + rin;
    const int b_kb = (grp & 1) << 4;
    const int v_rowb = ((grp & 1) << 3) + rin;
    const int v_cb = (grp >> 1) << 4;

    float sc[16][4];
    float oacc[8][4];
    #pragma unroll
    for (int i = 0; i < 8; i++)
        #pragma unroll
        for (int j = 0; j < 4; j++) oacc[i][j] = 0.0f;
    float m1 = -INFINITY, m2 = -INFINITY, l1 = 0.0f, l2 = 0.0f;

    #pragma unroll 1
    for (int kt = 0; kt < 8; kt++) {
        __syncthreads();
        {
            size_t tb = hbase + (size_t)kt * 128 * 64;
            const uint4* skh = (const uint4*)(kh + tb);
            const uint4* skl = (const uint4*)(kl + tb);
            const uint4* svh = (const uint4*)(vh + tb);
            const uint4* svl = (const uint4*)(vl + tb);
            #pragma unroll
            for (int i = 0; i < 4; i++) {
                int c = tid + i * 256;
                uint32_t d = SW128(c * 16);
                uint4 x;
                x = skh[c]; sts128(sb + KH + d, x.x, x.y, x.z, x.w);
                x = skl[c]; sts128(sb + KL + d, x.x, x.y, x.z, x.w);
                x = svh[c]; sts128(sb + VH + d, x.x, x.y, x.z, x.w);
                x = svl[c]; sts128(sb + VL + d, x.x, x.y, x.z, x.w);
            }
        }
        __syncthreads();

        #pragma unroll
        for (int j = 0; j < 16; j++)
            #pragma unroll
            for (int c = 0; c < 4; c++) sc[j][c] = 0.0f;
        #pragma unroll
        for (int ks = 0; ks < 4; ks++) {
            #pragma unroll
            for (int nb = 0; nb < 8; nb++) {
                uint32_t kfh[4], kfl[4];
                uint32_t off = (nb * 16 + b_rowb) * 128 + ks * 32 + b_kb;
                LDSM4(kfh, sb + KH + SW128(off));
                LDSM4(kfl, sb + KL + SW128(off));
                #pragma unroll
                for (int sub = 0; sub < 2; sub++) {
                    float* d = sc[nb * 2 + sub];
                    MMA_BF16(d, qfh[ks], kfh[sub * 2], kfh[sub * 2 + 1]);
                    MMA_BF16(d, qfl[ks], kfh[sub * 2], kfh[sub * 2 + 1]);
                    MMA_BF16(d, qfh[ks], kfl[sub * 2], kfl[sub * 2 + 1]);
                }
            }
        }

        float tm1 = -INFINITY, tm2 = -INFINITY;
        #pragma unroll
        for (int j = 0; j < 16; j++) {
            tm1 = fmaxf(tm1, fmaxf(sc[j][0], sc[j][1]));
            tm2 = fmaxf(tm2, fmaxf(sc[j][2], sc[j][3]));
        }
        tm1 = fmaxf(tm1, __shfl_xor_sync(0xffffffffu, tm1, 1));
        tm1 = fmaxf(tm1, __shfl_xor_sync(0xffffffffu, tm1, 2));
        tm2 = fmaxf(tm2, __shfl_xor_sync(0xffffffffu, tm2, 1));
        tm2 = fmaxf(tm2, __shfl_xor_sync(0xffffffffu, tm2, 2));

        float mn1 = fmaxf(m1, tm1), mn2 = fmaxf(m2, tm2);
        float al1 = __expf(m1 - mn1), al2 = __expf(m2 - mn2);
        m1 = mn1; m2 = mn2;

        float s1 = 0.0f, s2 = 0.0f;
        #pragma unroll
        for (int j = 0; j < 16; j++) {
            sc[j][0] = __expf(sc[j][0] - mn1);
            sc[j][1] = __expf(sc[j][1] - mn1);
            s1 += sc[j][0] + sc[j][1];
            sc[j][2] = __expf(sc[j][2] - mn2);
            sc[j][3] = __expf(sc[j][3] - mn2);
            s2 += sc[j][2] + sc[j][3];
        }
        s1 += __shfl_xor_sync(0xffffffffu, s1, 1);
        s1 += __shfl_xor_sync(0xffffffffu, s1, 2);
        s2 += __shfl_xor_sync(0xffffffffu, s2, 1);
        s2 += __shfl_xor_sync(0xffffffffu, s2, 2);
        l1 = l1 * al1 + s1;
        l2 = l2 * al2 + s2;
        #pragma unroll
        for (int nb = 0; nb < 8; nb++) {
            oacc[nb][0] *= al1; oacc[nb][1] *= al1;
            oacc[nb][2] *= al2; oacc[nb][3] *= al2;
        }

        #pragma unroll
        for (int ksv = 0; ksv < 8; ksv++) {
            uint32_t pah[4], pal[4];
            const int j0 = 2 * ksv, j1 = j0 + 1;
            cvt_pair(sc[j0][0], sc[j0][1], pah[0], pal[0]);
            cvt_pair(sc[j0][2], sc[j0][3], pah[1], pal[1]);
            cvt_pair(sc[j1][0], sc[j1][1], pah[2], pal[2]);
            cvt_pair(sc[j1][2], sc[j1][3], pah[3], pal[3]);
            #pragma unroll
            for (int nv = 0; nv < 4; nv++) {
                uint32_t vfh[4], vfl[4];
                uint32_t off = (ksv * 16 + v_rowb) * 128 + nv * 32 + v_cb;
                LDSM4T(vfh, sb + VH + SW128(off));
                LDSM4T(vfl, sb + VL + SW128(off));
                #pragma unroll
                for (int sub = 0; sub < 2; sub++) {
                    float* d = oacc[nv * 2 + sub];
                    MMA_BF16(d, pah, vfh[sub * 2], vfh[sub * 2 + 1]);
                    MMA_BF16(d, pal, vfh[sub * 2], vfh[sub * 2 + 1]);
                    MMA_BF16(d, pah, vfl[sub * 2], vfl[sub * 2 + 1]);
                }
            }
        }
    }

    // normalize + write ctx hi/lo bf16 [t*8+b][1024]
    const float inv1 = 1.0f / l1, inv2 = 1.0f / l2;
    const int t1 = q0 + wid * 16 + (lane >> 2);
    const int bb = head >> 4, hh = head & 15;
    const int colb = hh * 64 + 2 * (lane & 3);
    #pragma unroll
    for (int nb = 0; nb < 8; nb++) {
        int col = colb + nb * 8;
        size_t o1 = ((size_t)t1 * 8 + bb) * 1024 + col;
        uint32_t hw, lw;
        cvt_pair(oacc[nb][0] * inv1, oacc[nb][1] * inv1, hw, lw);
        *(uint32_t*)&ch[o1] = hw;
        *(uint32_t*)&cl[o1] = lw;
        cvt_pair(oacc[nb][2] * inv2, oacc[nb][3] * inv2, hw, lw);
        *(uint32_t*)&ch[o1 + 65536] = hw;   // t1+8 -> +64 rows
        *(uint32_t*)&cl[o1 + 65536] = lw;
    }
}

// ===========================================================================
// Launch
// ===========================================================================
extern "C" void kernel_launch(void* const* d_in, const int* in_sizes, int n_in,
                              void* d_out, int out_size) {
    const float* query = (const float*)d_in[0];
    const float* key   = (const float*)d_in[1];
    const float* value = (const float*)d_in[2];
    const float* Wq = (const float*)d_in[3];
    const float* bq = (const float*)d_in[4];
    const float* Wk = (const float*)d_in[5];
    const float* bk = (const float*)d_in[6];
    const float* Wv = (const float*)d_in[7];
    const float* bv = (const float*)d_in[8];
    const float* Wo = (const float*)d_in[9];
    const float* bo = (const float*)d_in[10];
    float* out = (float*)d_out;

    __nv_bfloat16 *pqh, *pql, *pkh, *pkl, *pvh, *pvl;
    __nv_bfloat16 *xh, *xl, *wh, *wl, *ch, *cl;
    cudaGetSymbolAddress((void**)&pqh, g_qh);
    cudaGetSymbolAddress((void**)&pql, g_ql);
    cudaGetSymbolAddress((void**)&pkh, g_kh);
    cudaGetSymbolAddress((void**)&pkl, g_kl);
    cudaGetSymbolAddress((void**)&pvh, g_vh);
    cudaGetSymbolAddress((void**)&pvl, g_vl);
    cudaGetSymbolAddress((void**)&xh, g_xh);
    cudaGetSymbolAddress((void**)&xl, g_xl);
    cudaGetSymbolAddress((void**)&wh, g_wh);
    cudaGetSymbolAddress((void**)&wl, g_wl);
    cudaGetSymbolAddress((void**)&ch, g_ch);
    cudaGetSymbolAddress((void**)&cl, g_cl);

    cudaFuncSetAttribute(gemm_tc_kernel,
                         cudaFuncAttributeMaxDynamicSharedMemorySize, GEMM_SMEM);
    cudaFuncSetAttribute(attn_tc_kernel,
                         cudaFuncAttributeMaxDynamicSharedMemorySize, ATTN_SMEM);

    const int n4_in = M_ROWS * D_DIM / 4;   // 2097152
    const int n4_w  = D_DIM * D_DIM / 4;    // 262144
    dim3 gemm_grid(1024 / 128, M_ROWS / 128);   // (8, 64)

    // Q projection
    cvt_kernel<<<n4_in / 256, 256>>>(query, xh, xl, n4_in);
    cvt_kernel<<<n4_w / 256, 256>>>(Wq, wh, wl, n4_w);
    gemm_tc_kernel<<<gemm_grid, 256, GEMM_SMEM>>>(xh, xl, wh, wl, bq, nullptr,
                                                  pqh, pql, 0.125f);
    // K projection
    cvt_kernel<<<n4_in / 256, 256>>>(key, xh, xl, n4_in);
    cvt_kernel<<<n4_w / 256, 256>>>(Wk, wh, wl, n4_w);
    gemm_tc_kernel<<<gemm_grid, 256, GEMM_SMEM>>>(xh, xl, wh, wl, bk, nullptr,
                                                  pkh, pkl, 1.0f);
    // V projection
    cvt_kernel<<<n4_in / 256, 256>>>(value, xh, xl, n4_in);
    cvt_kernel<<<n4_w / 256, 256>>>(Wv, wh, wl, n4_w);
    gemm_tc_kernel<<<gemm_grid, 256, GEMM_SMEM>>>(xh, xl, wh, wl, bv, nullptr,
                                                  pvh, pvl, 1.0f);

    // Attention -> ctx hi/lo planes
    dim3 attn_grid(T_DIM / 128, B_DIM * H_DIM);  // (8, 128)
    attn_tc_kernel<<<attn_grid, 256, ATTN_SMEM>>>(pqh, pql, pkh, pkl,
                                                  pvh, pvl, ch, cl);

    // O projection
    cvt_kernel<<<n4_w / 256, 256>>>(Wo, wh, wl, n4_w);
    gemm_tc_kernel<<<gemm_grid, 256, GEMM_SMEM>>>(ch, cl, wh, wl, bo, out,
                                                  nullptr, nullptr, 1.0f);
}

// round 12
// speedup vs baseline: 1.1113x; 1.1113x over previous
#include <cuda_runtime.h>
#include <cuda_bf16.h>
#include <stdint.h>
#include <math.h>

// Problem constants
#define T_DIM 1024
#define B_DIM 8
#define D_DIM 1024
#define H_DIM 16
#define HD_DIM 64
#define M_ROWS (T_DIM * B_DIM)        // 8192

// Scratch (no cudaMalloc allowed)
#define PLANE_ELEMS (128 * 1024 * 64)
__device__ __nv_bfloat16 g_qh[PLANE_ELEMS], g_ql[PLANE_ELEMS];   // head planes
__device__ __nv_bfloat16 g_kh[PLANE_ELEMS], g_kl[PLANE_ELEMS];
__device__ __nv_bfloat16 g_vh[PLANE_ELEMS], g_vl[PLANE_ELEMS];
__device__ __nv_bfloat16 g_xh[3 * M_ROWS * D_DIM], g_xl[3 * M_ROWS * D_DIM];
__device__ __nv_bfloat16 g_wh[3 * D_DIM * D_DIM], g_wl[3 * D_DIM * D_DIM];
__device__ __nv_bfloat16 g_ch[M_ROWS * D_DIM], g_cl[M_ROWS * D_DIM];
__device__ float g_bias[3 * D_DIM];

// ===========================================================================
// Helpers
// ===========================================================================
__device__ __forceinline__ uint32_t smem_u32(const void* p) {
    uint32_t a;
    asm("{ .reg .u64 t; cvta.to.shared.u64 t, %1; cvt.u32.u64 %0, t; }"
        : "=r"(a) : "l"(p));
    return a;
}
#define SW128(o) ((o) ^ (((o) >> 3) & 0x70))

#define LDSM4(r, addr) \
    asm volatile("ldmatrix.sync.aligned.m8n8.x4.shared.b16 {%0,%1,%2,%3}, [%4];" \
        : "=r"((r)[0]), "=r"((r)[1]), "=r"((r)[2]), "=r"((r)[3]) : "r"(addr))

#define LDSM4T(r, addr) \
    asm volatile("ldmatrix.sync.aligned.m8n8.x4.trans.shared.b16 {%0,%1,%2,%3}, [%4];" \
        : "=r"((r)[0]), "=r"((r)[1]), "=r"((r)[2]), "=r"((r)[3]) : "r"(addr))

#define MMA_BF16(d, a, b0_, b1_) \
    asm volatile("mma.sync.aligned.m16n8k16.row.col.f32.bf16.bf16.f32 " \
        "{%0,%1,%2,%3}, {%4,%5,%6,%7}, {%8,%9}, {%0,%1,%2,%3};" \
        : "+f"((d)[0]), "+f"((d)[1]), "+f"((d)[2]), "+f"((d)[3]) \
        : "r"((a)[0]), "r"((a)[1]), "r"((a)[2]), "r"((a)[3]), \
          "r"(b0_), "r"(b1_))

__device__ __forceinline__ void sts128(uint32_t addr, uint32_t a, uint32_t b,
                                       uint32_t c, uint32_t d) {
    asm volatile("st.shared.v4.b32 [%0], {%1,%2,%3,%4};"
                 :: "r"(addr), "r"(a), "r"(b), "r"(c), "r"(d) : "memory");
}
__device__ __forceinline__ void cvt_pair(float f0, float f1,
                                         uint32_t& hw, uint32_t& lw) {
    __nv_bfloat162 h = __floats2bfloat162_rn(f0, f1);
    float g0 = __bfloat162float(__low2bfloat16(h));
    float g1 = __bfloat162float(__high2bfloat16(h));
    __nv_bfloat162 l = __floats2bfloat162_rn(f0 - g0, f1 - g1);
    hw = *reinterpret_cast<uint32_t*>(&h);
    lw = *reinterpret_cast<uint32_t*>(&l);
}

// ===========================================================================
// Preconvert: fp32 -> hi/lo bf16 planes (4 float4 per thread)
// ===========================================================================
__global__ __launch_bounds__(256) void cvt_kernel(
    const float* __restrict__ src, __nv_bfloat16* __restrict__ h,
    __nv_bfloat16* __restrict__ l, int n4) {
    const int stride = gridDim.x * 256;
    for (int i = blockIdx.x * 256 + threadIdx.x; i < n4; i += stride) {
        float4 v = ((const float4*)src)[i];
        uint32_t h0, h1, l0, l1;
        cvt_pair(v.x, v.y, h0, l0);
        cvt_pair(v.z, v.w, h1, l1);
        ((uint2*)h)[i] = make_uint2(h0, h1);
        ((uint2*)l)[i] = make_uint2(l0, l1);
    }
}

// ===========================================================================
// Split-bf16 warp-MMA GEMM v4.
// Stacked A [rows][1024] (rows = 128*gridDim.y), stacked W [(seg*1024)+n][1024].
// seg = blockIdx.y >> 6. Merged QKV path (C==nullptr): epilogue to head
// planes (seg-selected, q scaled 0.125). O path (C!=nullptr): fp32 C + bias.
// 3-stage cp.async pipeline, 2 CTAs/SM.
// ===========================================================================
#define NSTAGE 3
#define G_STAGE 32768
#define GEMM_SMEM (NSTAGE * G_STAGE)   // 98304

__global__ __launch_bounds__(256, 2) void gemm_tc_kernel(
    const __nv_bfloat16* __restrict__ Ah_, const __nv_bfloat16* __restrict__ Al_,
    const __nv_bfloat16* __restrict__ Wh_, const __nv_bfloat16* __restrict__ Wl_,
    const float* __restrict__ bias, float* __restrict__ C,
    __nv_bfloat16* __restrict__ qh, __nv_bfloat16* __restrict__ ql,
    __nv_bfloat16* __restrict__ kh, __nv_bfloat16* __restrict__ kl,
    __nv_bfloat16* __restrict__ vh, __nv_bfloat16* __restrict__ vl) {
    extern __shared__ char smem[];
    const uint32_t sb = smem_u32(smem);

    const int tid = threadIdx.x;
    const int wid = tid >> 5;
    const int lane = tid & 31;
    const int warp_m = wid >> 3;          // unused bits guard
    const int wm = wid >> 2;              // 0..1
    const int wn = wid & 3;               // 0..3
    const int seg = blockIdx.y >> 6;
    const int row0 = blockIdx.y * 128;                 // absolute A row
    const int wrow0 = seg * 1024 + blockIdx.x * 128;   // absolute W row
    const int col0 = blockIdx.x * 128;                 // col within segment
    (void)warp_m;

    const int grp = lane >> 3, rin = lane & 7;
    const int a_mrow = ((grp & 1) << 3) + rin;
    const int a_kb   = (grp >> 1) << 4;
    const int b_nrow = ((grp >> 1) << 3) + rin;
    const int b_kb   = (grp & 1) << 4;

    // cp.async geometry
    const int rbase = tid >> 2;           // 0..63
    const int cseg = tid & 3;
    const size_t offA0 = (size_t)(row0 + rbase) * 1024 + cseg * 8;
    const size_t offA1 = offA0 + (size_t)64 * 1024;
    const size_t offW0 = (size_t)(wrow0 + rbase) * 1024 + cseg * 8;
    const size_t offW1 = offW0 + (size_t)64 * 1024;
    const uint32_t s0 = SW128(rbase * 128 + cseg * 16);
    const uint32_t s1 = SW128((64 + rbase) * 128 + cseg * 16);
    const uint32_t s2 = SW128(rbase * 128 + 64 + cseg * 16);
    const uint32_t s3 = SW128((64 + rbase) * 128 + 64 + cseg * 16);

    auto issue_stage = [&](int s) {
        const int kb = s * 32;
        const uint32_t dst = sb + (s % NSTAGE) * G_STAGE;
        asm volatile("cp.async.cg.shared.global [%0], [%1], 16;" :: "r"(dst + s0), "l"(Ah_ + offA0 + kb));
        asm volatile("cp.async.cg.shared.global [%0], [%1], 16;" :: "r"(dst + s1), "l"(Ah_ + offA1 + kb));
        asm volatile("cp.async.cg.shared.global [%0], [%1], 16;" :: "r"(dst + s2), "l"(Al_ + offA0 + kb));
        asm volatile("cp.async.cg.shared.global [%0], [%1], 16;" :: "r"(dst + s3), "l"(Al_ + offA1 + kb));
        asm volatile("cp.async.cg.shared.global [%0], [%1], 16;" :: "r"(dst + 16384 + s0), "l"(Wh_ + offW0 + kb));
        asm volatile("cp.async.cg.shared.global [%0], [%1], 16;" :: "r"(dst + 16384 + s1), "l"(Wh_ + offW1 + kb));
        asm volatile("cp.async.cg.shared.global [%0], [%1], 16;" :: "r"(dst + 16384 + s2), "l"(Wl_ + offW0 + kb));
        asm volatile("cp.async.cg.shared.global [%0], [%1], 16;" :: "r"(dst + 16384 + s3), "l"(Wl_ + offW1 + kb));
        asm volatile("cp.async.commit_group;" ::: "memory");
    };

    float acc[4][4][4];
    #pragma unroll
    for (int i = 0; i < 4; i++)
        #pragma unroll
        for (int j = 0; j < 4; j++)
            #pragma unroll
            for (int k = 0; k < 4; k++) acc[i][j][k] = 0.0f;

    issue_stage(0);
    issue_stage(1);

    #pragma unroll 1
    for (int s = 0; s < 32; s++) {
        asm volatile("cp.async.wait_group %0;" :: "n"(NSTAGE - 2) : "memory");
        __syncthreads();
        if (s + 2 < 32) issue_stage(s + 2);
        else asm volatile("cp.async.commit_group;" ::: "memory");

        const uint32_t AsB = sb + (s % NSTAGE) * G_STAGE;
        const uint32_t BsB = AsB + 16384;
        #pragma unroll
        for (int ks = 0; ks < 2; ks++) {
            uint32_t ah[4][4], al[4][4], bh[2][4], bl[2][4];
            #pragma unroll
            for (int mt = 0; mt < 4; mt++) {
                int row = wm * 64 + mt * 16 + a_mrow;
                uint32_t off = row * 128 + ks * 32 + a_kb;
                LDSM4(ah[mt], AsB + SW128(off));
                LDSM4(al[mt], AsB + SW128(off + 64));
            }
            #pragma unroll
            for (int np = 0; np < 2; np++) {
                int row = wn * 32 + np * 16 + b_nrow;
                uint32_t off = row * 128 + ks * 32 + b_kb;
                LDSM4(bh[np], BsB + SW128(off));
                LDSM4(bl[np], BsB + SW128(off + 64));
            }
            #pragma unroll
            for (int mt = 0; mt < 4; mt++)
                #pragma unroll
                for (int np = 0; np < 2; np++)
                    #pragma unroll
                    for (int sub = 0; sub < 2; sub++) {
                        float* d = acc[mt][np * 2 + sub];
                        MMA_BF16(d, ah[mt], bh[np][sub * 2], bh[np][sub * 2 + 1]);
                        MMA_BF16(d, al[mt], bh[np][sub * 2], bh[np][sub * 2 + 1]);
                        MMA_BF16(d, ah[mt], bl[np][sub * 2], bl[np][sub * 2 + 1]);
                    }
        }
    }

    // Epilogue
    if (C != nullptr) {
        #pragma unroll
        for (int mt = 0; mt < 4; mt++) {
            int rg = row0 + wm * 64 + mt * 16 + (lane >> 2);
            #pragma unroll
            for (int nt = 0; nt < 4; nt++) {
                int cg = col0 + wn * 32 + nt * 8 + (lane & 3) * 2;
                float b0 = __ldg(&bias[cg]), b1 = __ldg(&bias[cg + 1]);
                float2 v0 = make_float2(acc[mt][nt][0] + b0, acc[mt][nt][1] + b1);
                float2 v1 = make_float2(acc[mt][nt][2] + b0, acc[mt][nt][3] + b1);
                *(float2*)&C[(size_t)rg * 1024 + cg] = v0;
                *(float2*)&C[(size_t)(rg + 8) * 1024 + cg] = v1;
            }
        }
    } else {
        __nv_bfloat16* Ph = seg == 0 ? qh : (seg == 1 ? kh : vh);
        __nv_bfloat16* Pl = seg == 0 ? ql : (seg == 1 ? kl : vl);
        const float scale = (seg == 0) ? 0.125f : 1.0f;
        const int ry = (blockIdx.y & 63) * 128;
        #pragma unroll
        for (int mt = 0; mt < 4; mt++) {
            int rg = ry + wm * 64 + mt * 16 + (lane >> 2);
            int t = rg >> 3, bb = rg & 7;
            #pragma unroll
            for (int nt = 0; nt < 4; nt++) {
                int cg = col0 + wn * 32 + nt * 8 + (lane & 3) * 2;
                int hh = cg >> 6, hd = cg & 63;
                size_t pb = ((size_t)(bb * 16 + hh)) * 65536 + (size_t)t * 64 + hd;
                float b0 = __ldg(&bias[seg * 1024 + cg]);
                float b1 = __ldg(&bias[seg * 1024 + cg + 1]);
                uint32_t hw, lw;
                cvt_pair((acc[mt][nt][0] + b0) * scale,
                         (acc[mt][nt][1] + b1) * scale, hw, lw);
                *(uint32_t*)&Ph[pb] = hw;
                *(uint32_t*)&Pl[pb] = lw;
                cvt_pair((acc[mt][nt][2] + b0) * scale,
                         (acc[mt][nt][3] + b1) * scale, hw, lw);
                *(uint32_t*)&Ph[pb + 64] = hw;
                *(uint32_t*)&Pl[pb + 64] = lw;
            }
        }
    }
}

// ===========================================================================
// Tensor-core flash attention (unchanged from R10/R11 core), split-bf16.
// ===========================================================================
#define ATTN_SMEM 98304

__global__ __launch_bounds__(256, 1) void attn_tc_kernel(
    const __nv_bfloat16* __restrict__ qh, const __nv_bfloat16* __restrict__ ql,
    const __nv_bfloat16* __restrict__ kh, const __nv_bfloat16* __restrict__ kl,
    const __nv_bfloat16* __restrict__ vh, const __nv_bfloat16* __restrict__ vl,
    __nv_bfloat16* __restrict__ ch, __nv_bfloat16* __restrict__ cl) {
    extern __shared__ char smem[];
    const uint32_t sb = smem_u32(smem);
    const int tid = threadIdx.x, wid = tid >> 5, lane = tid & 31;
    const int grp = lane >> 3, rin = lane & 7;
    const int head = blockIdx.y;
    const int q0 = blockIdx.x * 128;
    const size_t hbase = (size_t)head * 65536;

    enum { QH = 0, QL = 16384, KH = 32768, KL = 49152, VH = 65536, VL = 81920 };

    {
        const uint4* sh = (const uint4*)(qh + hbase + (size_t)q0 * 64);
        const uint4* sl = (const uint4*)(ql + hbase + (size_t)q0 * 64);
        #pragma unroll
        for (int i = 0; i < 4; i++) {
            int c = tid + i * 256;
            uint32_t d = SW128(c * 16);
            uint4 a = sh[c]; sts128(sb + QH + d, a.x, a.y, a.z, a.w);
            uint4 b = sl[c]; sts128(sb + QL + d, b.x, b.y, b.z, b.w);
        }
    }
    __syncthreads();

    const int a_row = wid * 16 + ((grp & 1) << 3) + rin;
    const int a_kb = (grp >> 1) << 4;
    uint32_t qfh[4][4], qfl[4][4];
    #pragma unroll
    for (int ks = 0; ks < 4; ks++) {
        uint32_t off = a_row * 128 + ks * 32 + a_kb;
        LDSM4(qfh[ks], sb + QH + SW128(off));
        LDSM4(qfl[ks], sb + QL + SW128(off));
    }

    const int b_rowb = ((grp >> 1) << 3) + rin;
    const int b_kb = (grp & 1) << 4;
    const int v_rowb = ((grp & 1) << 3) + rin;
    const int v_cb = (grp >> 1) << 4;

    float sc[16][4];
    float oacc[8][4];
    #pragma unroll
    for (int i = 0; i < 8; i++)
        #pragma unroll
        for (int j = 0; j < 4; j++) oacc[i][j] = 0.0f;
    float m1 = -INFINITY, m2 = -INFINITY, l1 = 0.0f, l2 = 0.0f;

    #pragma unroll 1
    for (int kt = 0; kt < 8; kt++) {
        __syncthreads();
        {
            size_t tb = hbase + (size_t)kt * 128 * 64;
            const uint4* skh = (const uint4*)(kh + tb);
            const uint4* skl = (const uint4*)(kl + tb);
            const uint4* svh = (const uint4*)(vh + tb);
            const uint4* svl = (const uint4*)(vl + tb);
            #pragma unroll
            for (int i = 0; i < 4; i++) {
                int c = tid + i * 256;
                uint32_t d = SW128(c * 16);
                uint4 x;
                x = skh[c]; sts128(sb + KH + d, x.x, x.y, x.z, x.w);
                x = skl[c]; sts128(sb + KL + d, x.x, x.y, x.z, x.w);
                x = svh[c]; sts128(sb + VH + d, x.x, x.y, x.z, x.w);
                x = svl[c]; sts128(sb + VL + d, x.x, x.y, x.z, x.w);
            }
        }
        __syncthreads();

        #pragma unroll
        for (int j = 0; j < 16; j++)
            #pragma unroll
            for (int c = 0; c < 4; c++) sc[j][c] = 0.0f;
        #pragma unroll
        for (int ks = 0; ks < 4; ks++) {
            #pragma unroll
            for (int nb = 0; nb < 8; nb++) {
                uint32_t kfh[4], kfl[4];
                uint32_t off = (nb * 16 + b_rowb) * 128 + ks * 32 + b_kb;
                LDSM4(kfh, sb + KH + SW128(off));
                LDSM4(kfl, sb + KL + SW128(off));
                #pragma unroll
                for (int sub = 0; sub < 2; sub++) {
                    float* d = sc[nb * 2 + sub];
                    MMA_BF16(d, qfh[ks], kfh[sub * 2], kfh[sub * 2 + 1]);
                    MMA_BF16(d, qfl[ks], kfh[sub * 2], kfh[sub * 2 + 1]);
                    MMA_BF16(d, qfh[ks], kfl[sub * 2], kfl[sub * 2 + 1]);
                }
            }
        }

        float tm1 = -INFINITY, tm2 = -INFINITY;
        #pragma unroll
        for (int j = 0; j < 16; j++) {
            tm1 = fmaxf(tm1, fmaxf(sc[j][0], sc[j][1]));
            tm2 = fmaxf(tm2, fmaxf(sc[j][2], sc[j][3]));
        }
        tm1 = fmaxf(tm1, __shfl_xor_sync(0xffffffffu, tm1, 1));
        tm1 = fmaxf(tm1, __shfl_xor_sync(0xffffffffu, tm1, 2));
        tm2 = fmaxf(tm2, __shfl_xor_sync(0xffffffffu, tm2, 1));
        tm2 = fmaxf(tm2, __shfl_xor_sync(0xffffffffu, tm2, 2));

        float mn1 = fmaxf(m1, tm1), mn2 = fmaxf(m2, tm2);
        float al1 = __expf(m1 - mn1), al2 = __expf(m2 - mn2);
        m1 = mn1; m2 = mn2;

        float s1 = 0.0f, s2 = 0.0f;
        #pragma unroll
        for (int j = 0; j < 16; j++) {
            sc[j][0] = __expf(sc[j][0] - mn1);
            sc[j][1] = __expf(sc[j][1] - mn1);
            s1 += sc[j][0] + sc[j][1];
            sc[j][2] = __expf(sc[j][2] - mn2);
            sc[j][3] = __expf(sc[j][3] - mn2);
            s2 += sc[j][2] + sc[j][3];
        }
        s1 += __shfl_xor_sync(0xffffffffu, s1, 1);
        s1 += __shfl_xor_sync(0xffffffffu, s1, 2);
        s2 += __shfl_xor_sync(0xffffffffu, s2, 1);
        s2 += __shfl_xor_sync(0xffffffffu, s2, 2);
        l1 = l1 * al1 + s1;
        l2 = l2 * al2 + s2;
        #pragma unroll
        for (int nb = 0; nb < 8; nb++) {
            oacc[nb][0] *= al1; oacc[nb][1] *= al1;
            oacc[nb][2] *= al2; oacc[nb][3] *= al2;
        }

        #pragma unroll
        for (int ksv = 0; ksv < 8; ksv++) {
            uint32_t pah[4], pal[4];
            const int j0 = 2 * ksv, j1 = j0 + 1;
            cvt_pair(sc[j0][0], sc[j0][1], pah[0], pal[0]);
            cvt_pair(sc[j0][2], sc[j0][3], pah[1], pal[1]);
            cvt_pair(sc[j1][0], sc[j1][1], pah[2], pal[2]);
            cvt_pair(sc[j1][2], sc[j1][3], pah[3], pal[3]);
            #pragma unroll
            for (int nv = 0; nv < 4; nv++) {
                uint32_t vfh[4], vfl[4];
                uint32_t off = (ksv * 16 + v_rowb) * 128 + nv * 32 + v_cb;
                LDSM4T(vfh, sb + VH + SW128(off));
                LDSM4T(vfl, sb + VL + SW128(off));
                #pragma unroll
                for (int sub = 0; sub < 2; sub++) {
                    float* d = oacc[nv * 2 + sub];
                    MMA_BF16(d, pah, vfh[sub * 2], vfh[sub * 2 + 1]);
                    MMA_BF16(d, pal, vfh[sub * 2], vfh[sub * 2 + 1]);
                    MMA_BF16(d, pah, vfl[sub * 2], vfl[sub * 2 + 1]);
                }
            }
        }
    }

    const float inv1 = 1.0f / l1, inv2 = 1.0f / l2;
    const int t1 = q0 + wid * 16 + (lane >> 2);
    const int bb = head >> 4, hh = head & 15;
    const int colb = hh * 64 + 2 * (lane & 3);
    #pragma unroll
    for (int nb = 0; nb < 8; nb++) {
        int col = colb + nb * 8;
        size_t o1 = ((size_t)t1 * 8 + bb) * 1024 + col;
        uint32_t hw, lw;
        cvt_pair(oacc[nb][0] * inv1, oacc[nb][1] * inv1, hw, lw);
        *(uint32_t*)&ch[o1] = hw;
        *(uint32_t*)&cl[o1] = lw;
        cvt_pair(oacc[nb][2] * inv2, oacc[nb][3] * inv2, hw, lw);
        *(uint32_t*)&ch[o1 + 65536] = hw;
        *(uint32_t*)&cl[o1 + 65536] = lw;
    }
}

// ===========================================================================
// Launch
// ===========================================================================
extern "C" void kernel_launch(void* const* d_in, const int* in_sizes, int n_in,
                              void* d_out, int out_size) {
    const float* query = (const float*)d_in[0];
    const float* key   = (const float*)d_in[1];
    const float* value = (const float*)d_in[2];
    const float* Wq = (const float*)d_in[3];
    const float* bq = (const float*)d_in[4];
    const float* Wk = (const float*)d_in[5];
    const float* bk = (const float*)d_in[6];
    const float* Wv = (const float*)d_in[7];
    const float* bv = (const float*)d_in[8];
    const float* Wo = (const float*)d_in[9];
    const float* bo = (const float*)d_in[10];
    float* out = (float*)d_out;

    __nv_bfloat16 *pqh, *pql, *pkh, *pkl, *pvh, *pvl;
    __nv_bfloat16 *xh, *xl, *wh, *wl, *ch, *cl;
    float* biasb;
    cudaGetSymbolAddress((void**)&pqh, g_qh);
    cudaGetSymbolAddress((void**)&pql, g_ql);
    cudaGetSymbolAddress((void**)&pkh, g_kh);
    cudaGetSymbolAddress((void**)&pkl, g_kl);
    cudaGetSymbolAddress((void**)&pvh, g_vh);
    cudaGetSymbolAddress((void**)&pvl, g_vl);
    cudaGetSymbolAddress((void**)&xh, g_xh);
    cudaGetSymbolAddress((void**)&xl, g_xl);
    cudaGetSymbolAddress((void**)&wh, g_wh);
    cudaGetSymbolAddress((void**)&wl, g_wl);
    cudaGetSymbolAddress((void**)&ch, g_ch);
    cudaGetSymbolAddress((void**)&cl, g_cl);
    cudaGetSymbolAddress((void**)&biasb, g_bias);

    cudaFuncSetAttribute(gemm_tc_kernel,
                         cudaFuncAttributeMaxDynamicSharedMemorySize, GEMM_SMEM);
    cudaFuncSetAttribute(attn_tc_kernel,
                         cudaFuncAttributeMaxDynamicSharedMemorySize, ATTN_SMEM);

    const int n4_in = M_ROWS * D_DIM / 4;   // 2097152
    const int n4_w  = D_DIM * D_DIM / 4;    // 262144
    const int IN_OFF = M_ROWS * D_DIM;      // 8388608
    const int W_OFF  = D_DIM * D_DIM;       // 1048576

    // Preconvert inputs + weights (stacked), concat biases
    cvt_kernel<<<n4_in / 1024, 256>>>(query, xh, xl, n4_in);
    cvt_kernel<<<n4_in / 1024, 256>>>(key, xh + IN_OFF, xl + IN_OFF, n4_in);
    cvt_kernel<<<n4_in / 1024, 256>>>(value, xh + 2 * IN_OFF, xl + 2 * IN_OFF, n4_in);
    cvt_kernel<<<n4_w / 1024, 256>>>(Wq, wh, wl, n4_w);
    cvt_kernel<<<n4_w / 1024, 256>>>(Wk, wh + W_OFF, wl + W_OFF, n4_w);
    cvt_kernel<<<n4_w / 1024, 256>>>(Wv, wh + 2 * W_OFF, wl + 2 * W_OFF, n4_w);
    cudaMemcpyAsync(biasb, bq, D_DIM * sizeof(float), cudaMemcpyDeviceToDevice);
    cudaMemcpyAsync(biasb + D_DIM, bk, D_DIM * sizeof(float), cudaMemcpyDeviceToDevice);
    cudaMemcpyAsync(biasb + 2 * D_DIM, bv, D_DIM * sizeof(float), cudaMemcpyDeviceToDevice);

    // Merged QKV projection: grid (8, 192) = 1536 CTAs
    dim3 qkv_grid(D_DIM / 128, 3 * M_ROWS / 128);
    gemm_tc_kernel<<<qkv_grid, 256, GEMM_SMEM>>>(xh, xl, wh, wl, biasb, nullptr,
                                                 pqh, pql, pkh, pkl, pvh, pvl);

    // Attention -> ctx hi/lo planes
    dim3 attn_grid(T_DIM / 128, B_DIM * H_DIM);
    attn_tc_kernel<<<attn_grid, 256, ATTN_SMEM>>>(pqh, pql, pkh, pkl,
                                                  pvh, pvl, ch, cl);

    // O projection (seg 0 of weight stack = Wo, converted after QKV GEMM)
    cvt_kernel<<<n4_w / 1024, 256>>>(Wo, wh, wl, n4_w);
    dim3 o_grid(D_DIM / 128, M_ROWS / 128);
    gemm_tc_kernel<<<o_grid, 256, GEMM_SMEM>>>(ch, cl, wh, wl, bo, out,
                                               pqh, pql, pkh, pkl, pvh, pvl);
}

// round 13
// speedup vs baseline: 1.1583x; 1.0422x over previous
#include <cuda_runtime.h>
#include <cuda_bf16.h>
#include <stdint.h>
#include <math.h>

// Problem constants
#define T_DIM 1024
#define B_DIM 8
#define D_DIM 1024
#define H_DIM 16
#define HD_DIM 64
#define M_ROWS (T_DIM * B_DIM)        // 8192

// Scratch (no cudaMalloc allowed)
#define PLANE_ELEMS (128 * 1024 * 64)
__device__ __nv_bfloat16 g_qh[PLANE_ELEMS], g_ql[PLANE_ELEMS];   // head planes
__device__ __nv_bfloat16 g_kh[PLANE_ELEMS], g_kl[PLANE_ELEMS];
__device__ __nv_bfloat16 g_vh[PLANE_ELEMS], g_vl[PLANE_ELEMS];
__device__ __nv_bfloat16 g_xh[3 * M_ROWS * D_DIM], g_xl[3 * M_ROWS * D_DIM];
__device__ __nv_bfloat16 g_wh[3 * D_DIM * D_DIM], g_wl[3 * D_DIM * D_DIM];
__device__ __nv_bfloat16 g_ch[M_ROWS * D_DIM], g_cl[M_ROWS * D_DIM];
__device__ float g_bias[3 * D_DIM];

// ===========================================================================
// Helpers
// ===========================================================================
__device__ __forceinline__ uint32_t smem_u32(const void* p) {
    uint32_t a;
    asm("{ .reg .u64 t; cvta.to.shared.u64 t, %1; cvt.u32.u64 %0, t; }"
        : "=r"(a) : "l"(p));
    return a;
}
#define SW128(o) ((o) ^ (((o) >> 3) & 0x70))

#define LDSM4(r, addr) \
    asm volatile("ldmatrix.sync.aligned.m8n8.x4.shared.b16 {%0,%1,%2,%3}, [%4];" \
        : "=r"((r)[0]), "=r"((r)[1]), "=r"((r)[2]), "=r"((r)[3]) : "r"(addr))

#define LDSM4T(r, addr) \
    asm volatile("ldmatrix.sync.aligned.m8n8.x4.trans.shared.b16 {%0,%1,%2,%3}, [%4];" \
        : "=r"((r)[0]), "=r"((r)[1]), "=r"((r)[2]), "=r"((r)[3]) : "r"(addr))

#define MMA_BF16(d, a, b0_, b1_) \
    asm volatile("mma.sync.aligned.m16n8k16.row.col.f32.bf16.bf16.f32 " \
        "{%0,%1,%2,%3}, {%4,%5,%6,%7}, {%8,%9}, {%0,%1,%2,%3};" \
        : "+f"((d)[0]), "+f"((d)[1]), "+f"((d)[2]), "+f"((d)[3]) \
        : "r"((a)[0]), "r"((a)[1]), "r"((a)[2]), "r"((a)[3]), \
          "r"(b0_), "r"(b1_))

__device__ __forceinline__ void sts128(uint32_t addr, uint32_t a, uint32_t b,
                                       uint32_t c, uint32_t d) {
    asm volatile("st.shared.v4.b32 [%0], {%1,%2,%3,%4};"
                 :: "r"(addr), "r"(a), "r"(b), "r"(c), "r"(d) : "memory");
}
__device__ __forceinline__ void cvt_pair(float f0, float f1,
                                         uint32_t& hw, uint32_t& lw) {
    __nv_bfloat162 h = __floats2bfloat162_rn(f0, f1);
    float g0 = __bfloat162float(__low2bfloat16(h));
    float g1 = __bfloat162float(__high2bfloat16(h));
    __nv_bfloat162 l = __floats2bfloat162_rn(f0 - g0, f1 - g1);
    hw = *reinterpret_cast<uint32_t*>(&h);
    lw = *reinterpret_cast<uint32_t*>(&l);
}

// ===========================================================================
// Preconvert: fp32 -> hi/lo bf16 planes
// ===========================================================================
__global__ __launch_bounds__(256) void cvt_kernel(
    const float* __restrict__ src, __nv_bfloat16* __restrict__ h,
    __nv_bfloat16* __restrict__ l, int n4) {
    const int stride = gridDim.x * 256;
    for (int i = blockIdx.x * 256 + threadIdx.x; i < n4; i += stride) {
        float4 v = ((const float4*)src)[i];
        uint32_t h0, h1, l0, l1;
        cvt_pair(v.x, v.y, h0, l0);
        cvt_pair(v.z, v.w, h1, l1);
        ((uint2*)h)[i] = make_uint2(h0, h1);
        ((uint2*)l)[i] = make_uint2(l0, l1);
    }
}

// ===========================================================================
// Split-bf16 warp-MMA GEMM v4 (unchanged from R12).
// ===========================================================================
#define NSTAGE 3
#define G_STAGE 32768
#define GEMM_SMEM (NSTAGE * G_STAGE)   // 98304

__global__ __launch_bounds__(256, 2) void gemm_tc_kernel(
    const __nv_bfloat16* __restrict__ Ah_, const __nv_bfloat16* __restrict__ Al_,
    const __nv_bfloat16* __restrict__ Wh_, const __nv_bfloat16* __restrict__ Wl_,
    const float* __restrict__ bias, float* __restrict__ C,
    __nv_bfloat16* __restrict__ qh, __nv_bfloat16* __restrict__ ql,
    __nv_bfloat16* __restrict__ kh, __nv_bfloat16* __restrict__ kl,
    __nv_bfloat16* __restrict__ vh, __nv_bfloat16* __restrict__ vl) {
    extern __shared__ char smem[];
    const uint32_t sb = smem_u32(smem);

    const int tid = threadIdx.x;
    const int wid = tid >> 5;
    const int lane = tid & 31;
    const int wm = wid >> 2;
    const int wn = wid & 3;
    const int seg = blockIdx.y >> 6;
    const int row0 = blockIdx.y * 128;
    const int wrow0 = seg * 1024 + blockIdx.x * 128;
    const int col0 = blockIdx.x * 128;

    const int grp = lane >> 3, rin = lane & 7;
    const int a_mrow = ((grp & 1) << 3) + rin;
    const int a_kb   = (grp >> 1) << 4;
    const int b_nrow = ((grp >> 1) << 3) + rin;
    const int b_kb   = (grp & 1) << 4;

    const int rbase = tid >> 2;
    const int cseg = tid & 3;
    const size_t offA0 = (size_t)(row0 + rbase) * 1024 + cseg * 8;
    const size_t offA1 = offA0 + (size_t)64 * 1024;
    const size_t offW0 = (size_t)(wrow0 + rbase) * 1024 + cseg * 8;
    const size_t offW1 = offW0 + (size_t)64 * 1024;
    const uint32_t s0 = SW128(rbase * 128 + cseg * 16);
    const uint32_t s1 = SW128((64 + rbase) * 128 + cseg * 16);
    const uint32_t s2 = SW128(rbase * 128 + 64 + cseg * 16);
    const uint32_t s3 = SW128((64 + rbase) * 128 + 64 + cseg * 16);

    auto issue_stage = [&](int s) {
        const int kb = s * 32;
        const uint32_t dst = sb + (s % NSTAGE) * G_STAGE;
        asm volatile("cp.async.cg.shared.global [%0], [%1], 16;" :: "r"(dst + s0), "l"(Ah_ + offA0 + kb));
        asm volatile("cp.async.cg.shared.global [%0], [%1], 16;" :: "r"(dst + s1), "l"(Ah_ + offA1 + kb));
        asm volatile("cp.async.cg.shared.global [%0], [%1], 16;" :: "r"(dst + s2), "l"(Al_ + offA0 + kb));
        asm volatile("cp.async.cg.shared.global [%0], [%1], 16;" :: "r"(dst + s3), "l"(Al_ + offA1 + kb));
        asm volatile("cp.async.cg.shared.global [%0], [%1], 16;" :: "r"(dst + 16384 + s0), "l"(Wh_ + offW0 + kb));
        asm volatile("cp.async.cg.shared.global [%0], [%1], 16;" :: "r"(dst + 16384 + s1), "l"(Wh_ + offW1 + kb));
        asm volatile("cp.async.cg.shared.global [%0], [%1], 16;" :: "r"(dst + 16384 + s2), "l"(Wl_ + offW0 + kb));
        asm volatile("cp.async.cg.shared.global [%0], [%1], 16;" :: "r"(dst + 16384 + s3), "l"(Wl_ + offW1 + kb));
        asm volatile("cp.async.commit_group;" ::: "memory");
    };

    float acc[4][4][4];
    #pragma unroll
    for (int i = 0; i < 4; i++)
        #pragma unroll
        for (int j = 0; j < 4; j++)
            #pragma unroll
            for (int k = 0; k < 4; k++) acc[i][j][k] = 0.0f;

    issue_stage(0);
    issue_stage(1);

    #pragma unroll 1
    for (int s = 0; s < 32; s++) {
        asm volatile("cp.async.wait_group %0;" :: "n"(NSTAGE - 2) : "memory");
        __syncthreads();
        if (s + 2 < 32) issue_stage(s + 2);
        else asm volatile("cp.async.commit_group;" ::: "memory");

        const uint32_t AsB = sb + (s % NSTAGE) * G_STAGE;
        const uint32_t BsB = AsB + 16384;
        #pragma unroll
        for (int ks = 0; ks < 2; ks++) {
            uint32_t ah[4][4], al[4][4], bh[2][4], bl[2][4];
            #pragma unroll
            for (int mt = 0; mt < 4; mt++) {
                int row = wm * 64 + mt * 16 + a_mrow;
                uint32_t off = row * 128 + ks * 32 + a_kb;
                LDSM4(ah[mt], AsB + SW128(off));
                LDSM4(al[mt], AsB + SW128(off + 64));
            }
            #pragma unroll
            for (int np = 0; np < 2; np++) {
                int row = wn * 32 + np * 16 + b_nrow;
                uint32_t off = row * 128 + ks * 32 + b_kb;
                LDSM4(bh[np], BsB + SW128(off));
                LDSM4(bl[np], BsB + SW128(off + 64));
            }
            #pragma unroll
            for (int mt = 0; mt < 4; mt++)
                #pragma unroll
                for (int np = 0; np < 2; np++)
                    #pragma unroll
                    for (int sub = 0; sub < 2; sub++) {
                        float* d = acc[mt][np * 2 + sub];
                        MMA_BF16(d, ah[mt], bh[np][sub * 2], bh[np][sub * 2 + 1]);
                        MMA_BF16(d, al[mt], bh[np][sub * 2], bh[np][sub * 2 + 1]);
                        MMA_BF16(d, ah[mt], bl[np][sub * 2], bl[np][sub * 2 + 1]);
                    }
        }
    }

    if (C != nullptr) {
        #pragma unroll
        for (int mt = 0; mt < 4; mt++) {
            int rg = row0 + wm * 64 + mt * 16 + (lane >> 2);
            #pragma unroll
            for (int nt = 0; nt < 4; nt++) {
                int cg = col0 + wn * 32 + nt * 8 + (lane & 3) * 2;
                float b0 = __ldg(&bias[cg]), b1 = __ldg(&bias[cg + 1]);
                float2 v0 = make_float2(acc[mt][nt][0] + b0, acc[mt][nt][1] + b1);
                float2 v1 = make_float2(acc[mt][nt][2] + b0, acc[mt][nt][3] + b1);
                *(float2*)&C[(size_t)rg * 1024 + cg] = v0;
                *(float2*)&C[(size_t)(rg + 8) * 1024 + cg] = v1;
            }
        }
    } else {
        __nv_bfloat16* Ph = seg == 0 ? qh : (seg == 1 ? kh : vh);
        __nv_bfloat16* Pl = seg == 0 ? ql : (seg == 1 ? kl : vl);
        const float scale = (seg == 0) ? 0.125f : 1.0f;
        const int ry = (blockIdx.y & 63) * 128;
        #pragma unroll
        for (int mt = 0; mt < 4; mt++) {
            int rg = ry + wm * 64 + mt * 16 + (lane >> 2);
            int t = rg >> 3, bb = rg & 7;
            #pragma unroll
            for (int nt = 0; nt < 4; nt++) {
                int cg = col0 + wn * 32 + nt * 8 + (lane & 3) * 2;
                int hh = cg >> 6, hd = cg & 63;
                size_t pb = ((size_t)(bb * 16 + hh)) * 65536 + (size_t)t * 64 + hd;
                float b0 = __ldg(&bias[seg * 1024 + cg]);
                float b1 = __ldg(&bias[seg * 1024 + cg + 1]);
                uint32_t hw, lw;
                cvt_pair((acc[mt][nt][0] + b0) * scale,
                         (acc[mt][nt][1] + b1) * scale, hw, lw);
                *(uint32_t*)&Ph[pb] = hw;
                *(uint32_t*)&Pl[pb] = lw;
                cvt_pair((acc[mt][nt][2] + b0) * scale,
                         (acc[mt][nt][3] + b1) * scale, hw, lw);
                *(uint32_t*)&Ph[pb + 64] = hw;
                *(uint32_t*)&Pl[pb + 64] = lw;
            }
        }
    }
}

// ===========================================================================
// Tensor-core flash attention with cp.async double-buffered K/V.
// SMEM: QH 0 | QL 16K | stage0 {KH,KL,VH,VL} @32K | stage1 @96K  = 160 KB
// ===========================================================================
#define ATTN_SMEM 163840

__global__ __launch_bounds__(256, 1) void attn_tc_kernel(
    const __nv_bfloat16* __restrict__ qh, const __nv_bfloat16* __restrict__ ql,
    const __nv_bfloat16* __restrict__ kh, const __nv_bfloat16* __restrict__ kl,
    const __nv_bfloat16* __restrict__ vh, const __nv_bfloat16* __restrict__ vl,
    __nv_bfloat16* __restrict__ ch, __nv_bfloat16* __restrict__ cl) {
    extern __shared__ char smem[];
    const uint32_t sb = smem_u32(smem);
    const int tid = threadIdx.x, wid = tid >> 5, lane = tid & 31;
    const int grp = lane >> 3, rin = lane & 7;
    const int head = blockIdx.y;
    const int q0 = blockIdx.x * 128;
    const size_t hbase = (size_t)head * 65536;

    enum { QH = 0, QL = 16384, STAGE0 = 32768, STAGE_SZ = 65536 };
    enum { KHo = 0, KLo = 16384, VHo = 32768, VLo = 49152 };

    // Load Q hi/lo (one-time, synchronous)
    {
        const uint4* sh = (const uint4*)(qh + hbase + (size_t)q0 * 64);
        const uint4* sl = (const uint4*)(ql + hbase + (size_t)q0 * 64);
        #pragma unroll
        for (int i = 0; i < 4; i++) {
            int c = tid + i * 256;
            uint32_t d = SW128(c * 16);
            uint4 a = sh[c]; sts128(sb + QH + d, a.x, a.y, a.z, a.w);
            uint4 b = sl[c]; sts128(sb + QL + d, b.x, b.y, b.z, b.w);
        }
    }

    // K/V tile async loader
    auto issue_kv = [&](int kt) {
        const uint32_t st = sb + STAGE0 + (kt & 1) * STAGE_SZ;
        const size_t tb = hbase + (size_t)kt * 8192;   // 128*64 elems
        const __nv_bfloat16* pkh = kh + tb;
        const __nv_bfloat16* pkl = kl + tb;
        const __nv_bfloat16* pvh = vh + tb;
        const __nv_bfloat16* pvl = vl + tb;
        #pragma unroll
        for (int i = 0; i < 4; i++) {
            int c = tid + i * 256;
            uint32_t d = SW128(c * 16);
            asm volatile("cp.async.cg.shared.global [%0], [%1], 16;" :: "r"(st + KHo + d), "l"(pkh + c * 8));
            asm volatile("cp.async.cg.shared.global [%0], [%1], 16;" :: "r"(st + KLo + d), "l"(pkl + c * 8));
            asm volatile("cp.async.cg.shared.global [%0], [%1], 16;" :: "r"(st + VHo + d), "l"(pvh + c * 8));
            asm volatile("cp.async.cg.shared.global [%0], [%1], 16;" :: "r"(st + VLo + d), "l"(pvl + c * 8));
        }
        asm volatile("cp.async.commit_group;" ::: "memory");
    };

    issue_kv(0);
    __syncthreads();   // Q visible

    // Resident Q A-frags
    const int a_row = wid * 16 + ((grp & 1) << 3) + rin;
    const int a_kb = (grp >> 1) << 4;
    uint32_t qfh[4][4], qfl[4][4];
    #pragma unroll
    for (int ks = 0; ks < 4; ks++) {
        uint32_t off = a_row * 128 + ks * 32 + a_kb;
        LDSM4(qfh[ks], sb + QH + SW128(off));
        LDSM4(qfl[ks], sb + QL + SW128(off));
    }

    const int b_rowb = ((grp >> 1) << 3) + rin;
    const int b_kb = (grp & 1) << 4;
    const int v_rowb = ((grp & 1) << 3) + rin;
    const int v_cb = (grp >> 1) << 4;

    float sc[16][4];
    float oacc[8][4];
    #pragma unroll
    for (int i = 0; i < 8; i++)
        #pragma unroll
        for (int j = 0; j < 4; j++) oacc[i][j] = 0.0f;
    float m1 = -INFINITY, m2 = -INFINITY, l1 = 0.0f, l2 = 0.0f;

    #pragma unroll 1
    for (int kt = 0; kt < 8; kt++) {
        __syncthreads();    // all warps done reading buffer (kt+1)&1 from kt-1
        if (kt < 7) {
            issue_kv(kt + 1);
            asm volatile("cp.async.wait_group 1;" ::: "memory");
        } else {
            asm volatile("cp.async.wait_group 0;" ::: "memory");
        }
        __syncthreads();    // tile kt visible to all warps

        const uint32_t st = sb + STAGE0 + (kt & 1) * STAGE_SZ;

        // ---- S = Q K^T ----
        #pragma unroll
        for (int j = 0; j < 16; j++)
            #pragma unroll
            for (int c = 0; c < 4; c++) sc[j][c] = 0.0f;
        #pragma unroll
        for (int ks = 0; ks < 4; ks++) {
            #pragma unroll
            for (int nb = 0; nb < 8; nb++) {
                uint32_t kfh[4], kfl[4];
                uint32_t off = (nb * 16 + b_rowb) * 128 + ks * 32 + b_kb;
                LDSM4(kfh, st + KHo + SW128(off));
                LDSM4(kfl, st + KLo + SW128(off));
                #pragma unroll
                for (int sub = 0; sub < 2; sub++) {
                    float* d = sc[nb * 2 + sub];
                    MMA_BF16(d, qfh[ks], kfh[sub * 2], kfh[sub * 2 + 1]);
                    MMA_BF16(d, qfl[ks], kfh[sub * 2], kfh[sub * 2 + 1]);
                    MMA_BF16(d, qfh[ks], kfl[sub * 2], kfl[sub * 2 + 1]);
                }
            }
        }

        // ---- online softmax ----
        float tm1 = -INFINITY, tm2 = -INFINITY;
        #pragma unroll
        for (int j = 0; j < 16; j++) {
            tm1 = fmaxf(tm1, fmaxf(sc[j][0], sc[j][1]));
            tm2 = fmaxf(tm2, fmaxf(sc[j][2], sc[j][3]));
        }
        tm1 = fmaxf(tm1, __shfl_xor_sync(0xffffffffu, tm1, 1));
        tm1 = fmaxf(tm1, __shfl_xor_sync(0xffffffffu, tm1, 2));
        tm2 = fmaxf(tm2, __shfl_xor_sync(0xffffffffu, tm2, 1));
        tm2 = fmaxf(tm2, __shfl_xor_sync(0xffffffffu, tm2, 2));

        float mn1 = fmaxf(m1, tm1), mn2 = fmaxf(m2, tm2);
        float al1 = __expf(m1 - mn1), al2 = __expf(m2 - mn2);
        m1 = mn1; m2 = mn2;

        float s1 = 0.0f, s2 = 0.0f;
        #pragma unroll
        for (int j = 0; j < 16; j++) {
            sc[j][0] = __expf(sc[j][0] - mn1);
            sc[j][1] = __expf(sc[j][1] - mn1);
            s1 += sc[j][0] + sc[j][1];
            sc[j][2] = __expf(sc[j][2] - mn2);
            sc[j][3] = __expf(sc[j][3] - mn2);
            s2 += sc[j][2] + sc[j][3];
        }
        s1 += __shfl_xor_sync(0xffffffffu, s1, 1);
        s1 += __shfl_xor_sync(0xffffffffu, s1, 2);
        s2 += __shfl_xor_sync(0xffffffffu, s2, 1);
        s2 += __shfl_xor_sync(0xffffffffu, s2, 2);
        l1 = l1 * al1 + s1;
        l2 = l2 * al2 + s2;
        #pragma unroll
        for (int nb = 0; nb < 8; nb++) {
            oacc[nb][0] *= al1; oacc[nb][1] *= al1;
            oacc[nb][2] *= al2; oacc[nb][3] *= al2;
        }

        // ---- O += P V ----
        #pragma unroll
        for (int ksv = 0; ksv < 8; ksv++) {
            uint32_t pah[4], pal[4];
            const int j0 = 2 * ksv, j1 = j0 + 1;
            cvt_pair(sc[j0][0], sc[j0][1], pah[0], pal[0]);
            cvt_pair(sc[j0][2], sc[j0][3], pah[1], pal[1]);
            cvt_pair(sc[j1][0], sc[j1][1], pah[2], pal[2]);
            cvt_pair(sc[j1][2], sc[j1][3], pah[3], pal[3]);
            #pragma unroll
            for (int nv = 0; nv < 4; nv++) {
                uint32_t vfh[4], vfl[4];
                uint32_t off = (ksv * 16 + v_rowb) * 128 + nv * 32 + v_cb;
                LDSM4T(vfh, st + VHo + SW128(off));
                LDSM4T(vfl, st + VLo + SW128(off));
                #pragma unroll
                for (int sub = 0; sub < 2; sub++) {
                    float* d = oacc[nv * 2 + sub];
                    MMA_BF16(d, pah, vfh[sub * 2], vfh[sub * 2 + 1]);
                    MMA_BF16(d, pal, vfh[sub * 2], vfh[sub * 2 + 1]);
                    MMA_BF16(d, pah, vfl[sub * 2], vfl[sub * 2 + 1]);
                }
            }
        }
    }

    // ---- normalize + write ctx hi/lo bf16 [t*8+b][1024] ----
    const float inv1 = 1.0f / l1, inv2 = 1.0f / l2;
    const int t1 = q0 + wid * 16 + (lane >> 2);
    const int bb = head >> 4, hh = head & 15;
    const int colb = hh * 64 + 2 * (lane & 3);
    #pragma unroll
    for (int nb = 0; nb < 8; nb++) {
        int col = colb + nb * 8;
        size_t o1 = ((size_t)t1 * 8 + bb) * 1024 + col;
        uint32_t hw, lw;
        cvt_pair(oacc[nb][0] * inv1, oacc[nb][1] * inv1, hw, lw);
        *(uint32_t*)&ch[o1] = hw;
        *(uint32_t*)&cl[o1] = lw;
        cvt_pair(oacc[nb][2] * inv2, oacc[nb][3] * inv2, hw, lw);
        *(uint32_t*)&ch[o1 + 65536] = hw;
        *(uint32_t*)&cl[o1 + 65536] = lw;
    }
}

// ===========================================================================
// Launch
// ===========================================================================
extern "C" void kernel_launch(void* const* d_in, const int* in_sizes, int n_in,
                              void* d_out, int out_size) {
    const float* query = (const float*)d_in[0];
    const float* key   = (const float*)d_in[1];
    const float* value = (const float*)d_in[2];
    const float* Wq = (const float*)d_in[3];
    const float* bq = (const float*)d_in[4];
    const float* Wk = (const float*)d_in[5];
    const float* bk = (const float*)d_in[6];
    const float* Wv = (const float*)d_in[7];
    const float* bv = (const float*)d_in[8];
    const float* Wo = (const float*)d_in[9];
    const float* bo = (const float*)d_in[10];
    float* out = (float*)d_out;

    __nv_bfloat16 *pqh, *pql, *pkh, *pkl, *pvh, *pvl;
    __nv_bfloat16 *xh, *xl, *wh, *wl, *ch, *cl;
    float* biasb;
    cudaGetSymbolAddress((void**)&pqh, g_qh);
    cudaGetSymbolAddress((void**)&pql, g_ql);
    cudaGetSymbolAddress((void**)&pkh, g_kh);
    cudaGetSymbolAddress((void**)&pkl, g_kl);
    cudaGetSymbolAddress((void**)&pvh, g_vh);
    cudaGetSymbolAddress((void**)&pvl, g_vl);
    cudaGetSymbolAddress((void**)&xh, g_xh);
    cudaGetSymbolAddress((void**)&xl, g_xl);
    cudaGetSymbolAddress((void**)&wh, g_wh);
    cudaGetSymbolAddress((void**)&wl, g_wl);
    cudaGetSymbolAddress((void**)&ch, g_ch);
    cudaGetSymbolAddress((void**)&cl, g_cl);
    cudaGetSymbolAddress((void**)&biasb, g_bias);

    cudaFuncSetAttribute(gemm_tc_kernel,
                         cudaFuncAttributeMaxDynamicSharedMemorySize, GEMM_SMEM);
    cudaFuncSetAttribute(attn_tc_kernel,
                         cudaFuncAttributeMaxDynamicSharedMemorySize, ATTN_SMEM);

    const int n4_in = M_ROWS * D_DIM / 4;
    const int n4_w  = D_DIM * D_DIM / 4;
    const int IN_OFF = M_ROWS * D_DIM;
    const int W_OFF  = D_DIM * D_DIM;

    cvt_kernel<<<n4_in / 1024, 256>>>(query, xh, xl, n4_in);
    cvt_kernel<<<n4_in / 1024, 256>>>(key, xh + IN_OFF, xl + IN_OFF, n4_in);
    cvt_kernel<<<n4_in / 1024, 256>>>(value, xh + 2 * IN_OFF, xl + 2 * IN_OFF, n4_in);
    cvt_kernel<<<n4_w / 1024, 256>>>(Wq, wh, wl, n4_w);
    cvt_kernel<<<n4_w / 1024, 256>>>(Wk, wh + W_OFF, wl + W_OFF, n4_w);
    cvt_kernel<<<n4_w / 1024, 256>>>(Wv, wh + 2 * W_OFF, wl + 2 * W_OFF, n4_w);
    cudaMemcpyAsync(biasb, bq, D_DIM * sizeof(float), cudaMemcpyDeviceToDevice);
    cudaMemcpyAsync(biasb + D_DIM, bk, D_DIM * sizeof(float), cudaMemcpyDeviceToDevice);
    cudaMemcpyAsync(biasb + 2 * D_DIM, bv, D_DIM * sizeof(float), cudaMemcpyDeviceToDevice);

    dim3 qkv_grid(D_DIM / 128, 3 * M_ROWS / 128);
    gemm_tc_kernel<<<qkv_grid, 256, GEMM_SMEM>>>(xh, xl, wh, wl, biasb, nullptr,
                                                 pqh, pql, pkh, pkl, pvh, pvl);

    dim3 attn_grid(T_DIM / 128, B_DIM * H_DIM);
    attn_tc_kernel<<<attn_grid, 256, ATTN_SMEM>>>(pqh, pql, pkh, pkl,
                                                  pvh, pvl, ch, cl);

    cvt_kernel<<<n4_w / 1024, 256>>>(Wo, wh, wl, n4_w);
    dim3 o_grid(D_DIM / 128, M_ROWS / 128);
    gemm_tc_kernel<<<o_grid, 256, GEMM_SMEM>>>(ch, cl, wh, wl, bo, out,
                                               pqh, pql, pkh, pkl, pvh, pvl);
}

// round 14
// speedup vs baseline: 1.1768x; 1.0160x over previous
#include <cuda_runtime.h>
#include <cuda_bf16.h>
#include <stdint.h>
#include <math.h>

// Problem constants
#define T_DIM 1024
#define B_DIM 8
#define D_DIM 1024
#define H_DIM 16
#define HD_DIM 64
#define M_ROWS (T_DIM * B_DIM)        // 8192

// Scratch (no cudaMalloc allowed)
#define PLANE_ELEMS (128 * 1024 * 64)
__device__ __nv_bfloat16 g_qh[PLANE_ELEMS], g_ql[PLANE_ELEMS];   // head planes
__device__ __nv_bfloat16 g_kh[PLANE_ELEMS], g_kl[PLANE_ELEMS];
__device__ __nv_bfloat16 g_vh[PLANE_ELEMS], g_vl[PLANE_ELEMS];
__device__ __nv_bfloat16 g_xh[3 * M_ROWS * D_DIM], g_xl[3 * M_ROWS * D_DIM];
__device__ __nv_bfloat16 g_wh[4 * D_DIM * D_DIM], g_wl[4 * D_DIM * D_DIM];
__device__ __nv_bfloat16 g_ch[M_ROWS * D_DIM], g_cl[M_ROWS * D_DIM];
__device__ float g_bias[3 * D_DIM];

// ===========================================================================
// Helpers
// ===========================================================================
__device__ __forceinline__ uint32_t smem_u32(const void* p) {
    uint32_t a;
    asm("{ .reg .u64 t; cvta.to.shared.u64 t, %1; cvt.u32.u64 %0, t; }"
        : "=r"(a) : "l"(p));
    return a;
}
#define SW128(o) ((o) ^ (((o) >> 3) & 0x70))

#define LDSM4(r, addr) \
    asm volatile("ldmatrix.sync.aligned.m8n8.x4.shared.b16 {%0,%1,%2,%3}, [%4];" \
        : "=r"((r)[0]), "=r"((r)[1]), "=r"((r)[2]), "=r"((r)[3]) : "r"(addr))

#define LDSM4T(r, addr) \
    asm volatile("ldmatrix.sync.aligned.m8n8.x4.trans.shared.b16 {%0,%1,%2,%3}, [%4];" \
        : "=r"((r)[0]), "=r"((r)[1]), "=r"((r)[2]), "=r"((r)[3]) : "r"(addr))

#define MMA_BF16(d, a, b0_, b1_) \
    asm volatile("mma.sync.aligned.m16n8k16.row.col.f32.bf16.bf16.f32 " \
        "{%0,%1,%2,%3}, {%4,%5,%6,%7}, {%8,%9}, {%0,%1,%2,%3};" \
        : "+f"((d)[0]), "+f"((d)[1]), "+f"((d)[2]), "+f"((d)[3]) \
        : "r"((a)[0]), "r"((a)[1]), "r"((a)[2]), "r"((a)[3]), \
          "r"(b0_), "r"(b1_))

__device__ __forceinline__ void sts128(uint32_t addr, uint32_t a, uint32_t b,
                                       uint32_t c, uint32_t d) {
    asm volatile("st.shared.v4.b32 [%0], {%1,%2,%3,%4};"
                 :: "r"(addr), "r"(a), "r"(b), "r"(c), "r"(d) : "memory");
}
__device__ __forceinline__ void cvt_pair(float f0, float f1,
                                         uint32_t& hw, uint32_t& lw) {
    __nv_bfloat162 h = __floats2bfloat162_rn(f0, f1);
    float g0 = __bfloat162float(__low2bfloat16(h));
    float g1 = __bfloat162float(__high2bfloat16(h));
    __nv_bfloat162 l = __floats2bfloat162_rn(f0 - g0, f1 - g1);
    hw = *reinterpret_cast<uint32_t*>(&h);
    lw = *reinterpret_cast<uint32_t*>(&l);
}

// ===========================================================================
// Fused preconvert kernels: fp32 -> hi/lo bf16 planes.
// blockIdx.y selects the source tensor; dst is the stacked plane.
// ===========================================================================
__global__ __launch_bounds__(256) void cvt3_kernel(
    const float* __restrict__ s0, const float* __restrict__ s1,
    const float* __restrict__ s2,
    __nv_bfloat16* __restrict__ h, __nv_bfloat16* __restrict__ l, int n4seg) {
    const int segi = blockIdx.y;
    const float* s = (segi == 0) ? s0 : (segi == 1 ? s1 : s2);
    const int base = segi * n4seg;
    const int stride = gridDim.x * 256;
    for (int j = blockIdx.x * 256 + threadIdx.x; j < n4seg; j += stride) {
        float4 v = ((const float4*)s)[j];
        uint32_t h0, h1, l0, l1;
        cvt_pair(v.x, v.y, h0, l0);
        cvt_pair(v.z, v.w, h1, l1);
        ((uint2*)h)[base + j] = make_uint2(h0, h1);
        ((uint2*)l)[base + j] = make_uint2(l0, l1);
    }
}

__global__ __launch_bounds__(256) void cvt4_kernel(
    const float* __restrict__ s0, const float* __restrict__ s1,
    const float* __restrict__ s2, const float* __restrict__ s3,
    __nv_bfloat16* __restrict__ h, __nv_bfloat16* __restrict__ l, int n4seg) {
    const int segi = blockIdx.y;
    const float* s = (segi == 0) ? s0 : (segi == 1 ? s1 : (segi == 2 ? s2 : s3));
    const int base = segi * n4seg;
    const int stride = gridDim.x * 256;
    for (int j = blockIdx.x * 256 + threadIdx.x; j < n4seg; j += stride) {
        float4 v = ((const float4*)s)[j];
        uint32_t h0, h1, l0, l1;
        cvt_pair(v.x, v.y, h0, l0);
        cvt_pair(v.z, v.w, h1, l1);
        ((uint2*)h)[base + j] = make_uint2(h0, h1);
        ((uint2*)l)[base + j] = make_uint2(l0, l1);
    }
}

// ===========================================================================
// Split-bf16 warp-MMA GEMM v4 (unchanged from R13).
// ===========================================================================
#define NSTAGE 3
#define G_STAGE 32768
#define GEMM_SMEM (NSTAGE * G_STAGE)   // 98304

__global__ __launch_bounds__(256, 2) void gemm_tc_kernel(
    const __nv_bfloat16* __restrict__ Ah_, const __nv_bfloat16* __restrict__ Al_,
    const __nv_bfloat16* __restrict__ Wh_, const __nv_bfloat16* __restrict__ Wl_,
    const float* __restrict__ bias, float* __restrict__ C,
    __nv_bfloat16* __restrict__ qh, __nv_bfloat16* __restrict__ ql,
    __nv_bfloat16* __restrict__ kh, __nv_bfloat16* __restrict__ kl,
    __nv_bfloat16* __restrict__ vh, __nv_bfloat16* __restrict__ vl) {
    extern __shared__ char smem[];
    const uint32_t sb = smem_u32(smem);

    const int tid = threadIdx.x;
    const int wid = tid >> 5;
    const int lane = tid & 31;
    const int wm = wid >> 2;
    const int wn = wid & 3;
    const int seg = blockIdx.y >> 6;
    const int row0 = blockIdx.y * 128;
    const int wrow0 = seg * 1024 + blockIdx.x * 128;
    const int col0 = blockIdx.x * 128;

    const int grp = lane >> 3, rin = lane & 7;
    const int a_mrow = ((grp & 1) << 3) + rin;
    const int a_kb   = (grp >> 1) << 4;
    const int b_nrow = ((grp >> 1) << 3) + rin;
    const int b_kb   = (grp & 1) << 4;

    const int rbase = tid >> 2;
    const int cseg = tid & 3;
    const size_t offA0 = (size_t)(row0 + rbase) * 1024 + cseg * 8;
    const size_t offA1 = offA0 + (size_t)64 * 1024;
    const size_t offW0 = (size_t)(wrow0 + rbase) * 1024 + cseg * 8;
    const size_t offW1 = offW0 + (size_t)64 * 1024;
    const uint32_t s0 = SW128(rbase * 128 + cseg * 16);
    const uint32_t s1 = SW128((64 + rbase) * 128 + cseg * 16);
    const uint32_t s2 = SW128(rbase * 128 + 64 + cseg * 16);
    const uint32_t s3 = SW128((64 + rbase) * 128 + 64 + cseg * 16);

    auto issue_stage = [&](int s) {
        const int kb = s * 32;
        const uint32_t dst = sb + (s % NSTAGE) * G_STAGE;
        asm volatile("cp.async.cg.shared.global [%0], [%1], 16;" :: "r"(dst + s0), "l"(Ah_ + offA0 + kb));
        asm volatile("cp.async.cg.shared.global [%0], [%1], 16;" :: "r"(dst + s1), "l"(Ah_ + offA1 + kb));
        asm volatile("cp.async.cg.shared.global [%0], [%1], 16;" :: "r"(dst + s2), "l"(Al_ + offA0 + kb));
        asm volatile("cp.async.cg.shared.global [%0], [%1], 16;" :: "r"(dst + s3), "l"(Al_ + offA1 + kb));
        asm volatile("cp.async.cg.shared.global [%0], [%1], 16;" :: "r"(dst + 16384 + s0), "l"(Wh_ + offW0 + kb));
        asm volatile("cp.async.cg.shared.global [%0], [%1], 16;" :: "r"(dst + 16384 + s1), "l"(Wh_ + offW1 + kb));
        asm volatile("cp.async.cg.shared.global [%0], [%1], 16;" :: "r"(dst + 16384 + s2), "l"(Wl_ + offW0 + kb));
        asm volatile("cp.async.cg.shared.global [%0], [%1], 16;" :: "r"(dst + 16384 + s3), "l"(Wl_ + offW1 + kb));
        asm volatile("cp.async.commit_group;" ::: "memory");
    };

    float acc[4][4][4];
    #pragma unroll
    for (int i = 0; i < 4; i++)
        #pragma unroll
        for (int j = 0; j < 4; j++)
            #pragma unroll
            for (int k = 0; k < 4; k++) acc[i][j][k] = 0.0f;

    issue_stage(0);
    issue_stage(1);

    #pragma unroll 1
    for (int s = 0; s < 32; s++) {
        asm volatile("cp.async.wait_group %0;" :: "n"(NSTAGE - 2) : "memory");
        __syncthreads();
        if (s + 2 < 32) issue_stage(s + 2);
        else asm volatile("cp.async.commit_group;" ::: "memory");

        const uint32_t AsB = sb + (s % NSTAGE) * G_STAGE;
        const uint32_t BsB = AsB + 16384;
        #pragma unroll
        for (int ks = 0; ks < 2; ks++) {
            uint32_t ah[4][4], al[4][4], bh[2][4], bl[2][4];
            #pragma unroll
            for (int mt = 0; mt < 4; mt++) {
                int row = wm * 64 + mt * 16 + a_mrow;
                uint32_t off = row * 128 + ks * 32 + a_kb;
                LDSM4(ah[mt], AsB + SW128(off));
                LDSM4(al[mt], AsB + SW128(off + 64));
            }
            #pragma unroll
            for (int np = 0; np < 2; np++) {
                int row = wn * 32 + np * 16 + b_nrow;
                uint32_t off = row * 128 + ks * 32 + b_kb;
                LDSM4(bh[np], BsB + SW128(off));
                LDSM4(bl[np], BsB + SW128(off + 64));
            }
            #pragma unroll
            for (int mt = 0; mt < 4; mt++)
                #pragma unroll
                for (int np = 0; np < 2; np++)
                    #pragma unroll
                    for (int sub = 0; sub < 2; sub++) {
                        float* d = acc[mt][np * 2 + sub];
                        MMA_BF16(d, ah[mt], bh[np][sub * 2], bh[np][sub * 2 + 1]);
                        MMA_BF16(d, al[mt], bh[np][sub * 2], bh[np][sub * 2 + 1]);
                        MMA_BF16(d, ah[mt], bl[np][sub * 2], bl[np][sub * 2 + 1]);
                    }
        }
    }

    if (C != nullptr) {
        #pragma unroll
        for (int mt = 0; mt < 4; mt++) {
            int rg = row0 + wm * 64 + mt * 16 + (lane >> 2);
            #pragma unroll
            for (int nt = 0; nt < 4; nt++) {
                int cg = col0 + wn * 32 + nt * 8 + (lane & 3) * 2;
                float b0 = __ldg(&bias[cg]), b1 = __ldg(&bias[cg + 1]);
                float2 v0 = make_float2(acc[mt][nt][0] + b0, acc[mt][nt][1] + b1);
                float2 v1 = make_float2(acc[mt][nt][2] + b0, acc[mt][nt][3] + b1);
                *(float2*)&C[(size_t)rg * 1024 + cg] = v0;
                *(float2*)&C[(size_t)(rg + 8) * 1024 + cg] = v1;
            }
        }
    } else {
        __nv_bfloat16* Ph = seg == 0 ? qh : (seg == 1 ? kh : vh);
        __nv_bfloat16* Pl = seg == 0 ? ql : (seg == 1 ? kl : vl);
        const float scale = (seg == 0) ? 0.125f : 1.0f;
        const int ry = (blockIdx.y & 63) * 128;
        #pragma unroll
        for (int mt = 0; mt < 4; mt++) {
            int rg = ry + wm * 64 + mt * 16 + (lane >> 2);
            int t = rg >> 3, bb = rg & 7;
            #pragma unroll
            for (int nt = 0; nt < 4; nt++) {
                int cg = col0 + wn * 32 + nt * 8 + (lane & 3) * 2;
                int hh = cg >> 6, hd = cg & 63;
                size_t pb = ((size_t)(bb * 16 + hh)) * 65536 + (size_t)t * 64 + hd;
                float b0 = __ldg(&bias[seg * 1024 + cg]);
                float b1 = __ldg(&bias[seg * 1024 + cg + 1]);
                uint32_t hw, lw;
                cvt_pair((acc[mt][nt][0] + b0) * scale,
                         (acc[mt][nt][1] + b1) * scale, hw, lw);
                *(uint32_t*)&Ph[pb] = hw;
                *(uint32_t*)&Pl[pb] = lw;
                cvt_pair((acc[mt][nt][2] + b0) * scale,
                         (acc[mt][nt][3] + b1) * scale, hw, lw);
                *(uint32_t*)&Ph[pb + 64] = hw;
                *(uint32_t*)&Pl[pb + 64] = lw;
            }
        }
    }
}

// ===========================================================================
// Tensor-core flash attention with cp.async double-buffered K/V (R13).
// ===========================================================================
#define ATTN_SMEM 163840

__global__ __launch_bounds__(256, 1) void attn_tc_kernel(
    const __nv_bfloat16* __restrict__ qh, const __nv_bfloat16* __restrict__ ql,
    const __nv_bfloat16* __restrict__ kh, const __nv_bfloat16* __restrict__ kl,
    const __nv_bfloat16* __restrict__ vh, const __nv_bfloat16* __restrict__ vl,
    __nv_bfloat16* __restrict__ ch, __nv_bfloat16* __restrict__ cl) {
    extern __shared__ char smem[];
    const uint32_t sb = smem_u32(smem);
    const int tid = threadIdx.x, wid = tid >> 5, lane = tid & 31;
    const int grp = lane >> 3, rin = lane & 7;
    const int head = blockIdx.y;
    const int q0 = blockIdx.x * 128;
    const size_t hbase = (size_t)head * 65536;

    enum { QH = 0, QL = 16384, STAGE0 = 32768, STAGE_SZ = 65536 };
    enum { KHo = 0, KLo = 16384, VHo = 32768, VLo = 49152 };

    {
        const uint4* sh = (const uint4*)(qh + hbase + (size_t)q0 * 64);
        const uint4* sl = (const uint4*)(ql + hbase + (size_t)q0 * 64);
        #pragma unroll
        for (int i = 0; i < 4; i++) {
            int c = tid + i * 256;
            uint32_t d = SW128(c * 16);
            uint4 a = sh[c]; sts128(sb + QH + d, a.x, a.y, a.z, a.w);
            uint4 b = sl[c]; sts128(sb + QL + d, b.x, b.y, b.z, b.w);
        }
    }

    auto issue_kv = [&](int kt) {
        const uint32_t st = sb + STAGE0 + (kt & 1) * STAGE_SZ;
        const size_t tb = hbase + (size_t)kt * 8192;
        const __nv_bfloat16* pkh = kh + tb;
        const __nv_bfloat16* pkl = kl + tb;
        const __nv_bfloat16* pvh = vh + tb;
        const __nv_bfloat16* pvl = vl + tb;
        #pragma unroll
        for (int i = 0; i < 4; i++) {
            int c = tid + i * 256;
            uint32_t d = SW128(c * 16);
            asm volatile("cp.async.cg.shared.global [%0], [%1], 16;" :: "r"(st + KHo + d), "l"(pkh + c * 8));
            asm volatile("cp.async.cg.shared.global [%0], [%1], 16;" :: "r"(st + KLo + d), "l"(pkl + c * 8));
            asm volatile("cp.async.cg.shared.global [%0], [%1], 16;" :: "r"(st + VHo + d), "l"(pvh + c * 8));
            asm volatile("cp.async.cg.shared.global [%0], [%1], 16;" :: "r"(st + VLo + d), "l"(pvl + c * 8));
        }
        asm volatile("cp.async.commit_group;" ::: "memory");
    };

    issue_kv(0);
    __syncthreads();

    const int a_row = wid * 16 + ((grp & 1) << 3) + rin;
    const int a_kb = (grp >> 1) << 4;
    uint32_t qfh[4][4], qfl[4][4];
    #pragma unroll
    for (int ks = 0; ks < 4; ks++) {
        uint32_t off = a_row * 128 + ks * 32 + a_kb;
        LDSM4(qfh[ks], sb + QH + SW128(off));
        LDSM4(qfl[ks], sb + QL + SW128(off));
    }

    const int b_rowb = ((grp >> 1) << 3) + rin;
    const int b_kb = (grp & 1) << 4;
    const int v_rowb = ((grp & 1) << 3) + rin;
    const int v_cb = (grp >> 1) << 4;

    float sc[16][4];
    float oacc[8][4];
    #pragma unroll
    for (int i = 0; i < 8; i++)
        #pragma unroll
        for (int j = 0; j < 4; j++) oacc[i][j] = 0.0f;
    float m1 = -INFINITY, m2 = -INFINITY, l1 = 0.0f, l2 = 0.0f;

    #pragma unroll 1
    for (int kt = 0; kt < 8; kt++) {
        __syncthreads();
        if (kt < 7) {
            issue_kv(kt + 1);
            asm volatile("cp.async.wait_group 1;" ::: "memory");
        } else {
            asm volatile("cp.async.wait_group 0;" ::: "memory");
        }
        __syncthreads();

        const uint32_t st = sb + STAGE0 + (kt & 1) * STAGE_SZ;

        #pragma unroll
        for (int j = 0; j < 16; j++)
            #pragma unroll
            for (int c = 0; c < 4; c++) sc[j][c] = 0.0f;
        #pragma unroll
        for (int ks = 0; ks < 4; ks++) {
            #pragma unroll
            for (int nb = 0; nb < 8; nb++) {
                uint32_t kfh[4], kfl[4];
                uint32_t off = (nb * 16 + b_rowb) * 128 + ks * 32 + b_kb;
                LDSM4(kfh, st + KHo + SW128(off));
                LDSM4(kfl, st + KLo + SW128(off));
                #pragma unroll
                for (int sub = 0; sub < 2; sub++) {
                    float* d = sc[nb * 2 + sub];
                    MMA_BF16(d, qfh[ks], kfh[sub * 2], kfh[sub * 2 + 1]);
                    MMA_BF16(d, qfl[ks], kfh[sub * 2], kfh[sub * 2 + 1]);
                    MMA_BF16(d, qfh[ks], kfl[sub * 2], kfl[sub * 2 + 1]);
                }
            }
        }

        float tm1 = -INFINITY, tm2 = -INFINITY;
        #pragma unroll
        for (int j = 0; j < 16; j++) {
            tm1 = fmaxf(tm1, fmaxf(sc[j][0], sc[j][1]));
            tm2 = fmaxf(tm2, fmaxf(sc[j][2], sc[j][3]));
        }
        tm1 = fmaxf(tm1, __shfl_xor_sync(0xffffffffu, tm1, 1));
        tm1 = fmaxf(tm1, __shfl_xor_sync(0xffffffffu, tm1, 2));
        tm2 = fmaxf(tm2, __shfl_xor_sync(0xffffffffu, tm2, 1));
        tm2 = fmaxf(tm2, __shfl_xor_sync(0xffffffffu, tm2, 2));

        float mn1 = fmaxf(m1, tm1), mn2 = fmaxf(m2, tm2);
        float al1 = __expf(m1 - mn1), al2 = __expf(m2 - mn2);
        m1 = mn1; m2 = mn2;

        float s1 = 0.0f, s2 = 0.0f;
        #pragma unroll
        for (int j = 0; j < 16; j++) {
            sc[j][0] = __expf(sc[j][0] - mn1);
            sc[j][1] = __expf(sc[j][1] - mn1);
            s1 += sc[j][0] + sc[j][1];
            sc[j][2] = __expf(sc[j][2] - mn2);
            sc[j][3] = __expf(sc[j][3] - mn2);
            s2 += sc[j][2] + sc[j][3];
        }
        s1 += __shfl_xor_sync(0xffffffffu, s1, 1);
        s1 += __shfl_xor_sync(0xffffffffu, s1, 2);
        s2 += __shfl_xor_sync(0xffffffffu, s2, 1);
        s2 += __shfl_xor_sync(0xffffffffu, s2, 2);
        l1 = l1 * al1 + s1;
        l2 = l2 * al2 + s2;
        #pragma unroll
        for (int nb = 0; nb < 8; nb++) {
            oacc[nb][0] *= al1; oacc[nb][1] *= al1;
            oacc[nb][2] *= al2; oacc[nb][3] *= al2;
        }

        #pragma unroll
        for (int ksv = 0; ksv < 8; ksv++) {
            uint32_t pah[4], pal[4];
            const int j0 = 2 * ksv, j1 = j0 + 1;
            cvt_pair(sc[j0][0], sc[j0][1], pah[0], pal[0]);
            cvt_pair(sc[j0][2], sc[j0][3], pah[1], pal[1]);
            cvt_pair(sc[j1][0], sc[j1][1], pah[2], pal[2]);
            cvt_pair(sc[j1][2], sc[j1][3], pah[3], pal[3]);
            #pragma unroll
            for (int nv = 0; nv < 4; nv++) {
                uint32_t vfh[4], vfl[4];
                uint32_t off = (ksv * 16 + v_rowb) * 128 + nv * 32 + v_cb;
                LDSM4T(vfh, st + VHo + SW128(off));
                LDSM4T(vfl, st + VLo + SW128(off));
                #pragma unroll
                for (int sub = 0; sub < 2; sub++) {
                    float* d = oacc[nv * 2 + sub];
                    MMA_BF16(d, pah, vfh[sub * 2], vfh[sub * 2 + 1]);
                    MMA_BF16(d, pal, vfh[sub * 2], vfh[sub * 2 + 1]);
                    MMA_BF16(d, pah, vfl[sub * 2], vfl[sub * 2 + 1]);
                }
            }
        }
    }

    const float inv1 = 1.0f / l1, inv2 = 1.0f / l2;
    const int t1 = q0 + wid * 16 + (lane >> 2);
    const int bb = head >> 4, hh = head & 15;
    const int colb = hh * 64 + 2 * (lane & 3);
    #pragma unroll
    for (int nb = 0; nb < 8; nb++) {
        int col = colb + nb * 8;
        size_t o1 = ((size_t)t1 * 8 + bb) * 1024 + col;
        uint32_t hw, lw;
        cvt_pair(oacc[nb][0] * inv1, oacc[nb][1] * inv1, hw, lw);
        *(uint32_t*)&ch[o1] = hw;
        *(uint32_t*)&cl[o1] = lw;
        cvt_pair(oacc[nb][2] * inv2, oacc[nb][3] * inv2, hw, lw);
        *(uint32_t*)&ch[o1 + 65536] = hw;
        *(uint32_t*)&cl[o1 + 65536] = lw;
    }
}

// ===========================================================================
// Launch
// ===========================================================================
extern "C" void kernel_launch(void* const* d_in, const int* in_sizes, int n_in,
                              void* d_out, int out_size) {
    const float* query = (const float*)d_in[0];
    const float* key   = (const float*)d_in[1];
    const float* value = (const float*)d_in[2];
    const float* Wq = (const float*)d_in[3];
    const float* bq = (const float*)d_in[4];
    const float* Wk = (const float*)d_in[5];
    const float* bk = (const float*)d_in[6];
    const float* Wv = (const float*)d_in[7];
    const float* bv = (const float*)d_in[8];
    const float* Wo = (const float*)d_in[9];
    const float* bo = (const float*)d_in[10];
    float* out = (float*)d_out;

    __nv_bfloat16 *pqh, *pql, *pkh, *pkl, *pvh, *pvl;
    __nv_bfloat16 *xh, *xl, *wh, *wl, *ch, *cl;
    float* biasb;
    cudaGetSymbolAddress((void**)&pqh, g_qh);
    cudaGetSymbolAddress((void**)&pql, g_ql);
    cudaGetSymbolAddress((void**)&pkh, g_kh);
    cudaGetSymbolAddress((void**)&pkl, g_kl);
    cudaGetSymbolAddress((void**)&pvh, g_vh);
    cudaGetSymbolAddress((void**)&pvl, g_vl);
    cudaGetSymbolAddress((void**)&xh, g_xh);
    cudaGetSymbolAddress((void**)&xl, g_xl);
    cudaGetSymbolAddress((void**)&wh, g_wh);
    cudaGetSymbolAddress((void**)&wl, g_wl);
    cudaGetSymbolAddress((void**)&ch, g_ch);
    cudaGetSymbolAddress((void**)&cl, g_cl);
    cudaGetSymbolAddress((void**)&biasb, g_bias);

    cudaFuncSetAttribute(gemm_tc_kernel,
                         cudaFuncAttributeMaxDynamicSharedMemorySize, GEMM_SMEM);
    cudaFuncSetAttribute(attn_tc_kernel,
                         cudaFuncAttributeMaxDynamicSharedMemorySize, ATTN_SMEM);

    const int n4_in = M_ROWS * D_DIM / 4;   // 2097152 float4 per input
    const int n4_w  = D_DIM * D_DIM / 4;    // 262144 float4 per weight
    const int W_OFF  = D_DIM * D_DIM;

    // Fused preconversion: one launch for 3 inputs, one for 4 weights (incl Wo)
    cvt3_kernel<<<dim3(1024, 3), 256>>>(query, key, value, xh, xl, n4_in);
    cvt4_kernel<<<dim3(256, 4), 256>>>(Wq, Wk, Wv, Wo, wh, wl, n4_w);
    cudaMemcpyAsync(biasb, bq, D_DIM * sizeof(float), cudaMemcpyDeviceToDevice);
    cudaMemcpyAsync(biasb + D_DIM, bk, D_DIM * sizeof(float), cudaMemcpyDeviceToDevice);
    cudaMemcpyAsync(biasb + 2 * D_DIM, bv, D_DIM * sizeof(float), cudaMemcpyDeviceToDevice);

    // Merged QKV projection
    dim3 qkv_grid(D_DIM / 128, 3 * M_ROWS / 128);
    gemm_tc_kernel<<<qkv_grid, 256, GEMM_SMEM>>>(xh, xl, wh, wl, biasb, nullptr,
                                                 pqh, pql, pkh, pkl, pvh, pvl);

    // Attention -> ctx hi/lo planes
    dim3 attn_grid(T_DIM / 128, B_DIM * H_DIM);
    attn_tc_kernel<<<attn_grid, 256, ATTN_SMEM>>>(pqh, pql, pkh, pkl,
                                                  pvh, pvl, ch, cl);

    // O projection (Wo = segment 3 of the preconverted weight stack)
    dim3 o_grid(D_DIM / 128, M_ROWS / 128);
    gemm_tc_kernel<<<o_grid, 256, GEMM_SMEM>>>(ch, cl, wh + 3 * W_OFF, wl + 3 * W_OFF,
                                               bo, out,
                                               pqh, pql, pkh, pkl, pvh, pvl);
}

// round 15
// speedup vs baseline: 1.1776x; 1.0007x over previous
#include <cuda_runtime.h>
#include <cuda_bf16.h>
#include <stdint.h>
#include <math.h>

// Problem constants
#define T_DIM 1024
#define B_DIM 8
#define D_DIM 1024
#define H_DIM 16
#define HD_DIM 64
#define M_ROWS (T_DIM * B_DIM)        // 8192

// Scratch (no cudaMalloc allowed)
#define PLANE_ELEMS (128 * 1024 * 64)
__device__ __nv_bfloat16 g_qh[PLANE_ELEMS], g_ql[PLANE_ELEMS];   // head planes
__device__ __nv_bfloat16 g_kh[PLANE_ELEMS], g_kl[PLANE_ELEMS];
__device__ __nv_bfloat16 g_vh[PLANE_ELEMS], g_vl[PLANE_ELEMS];
__device__ __nv_bfloat16 g_xh[3 * M_ROWS * D_DIM], g_xl[3 * M_ROWS * D_DIM];
__device__ __nv_bfloat16 g_wh[4 * D_DIM * D_DIM], g_wl[4 * D_DIM * D_DIM];
__device__ __nv_bfloat16 g_ch[M_ROWS * D_DIM], g_cl[M_ROWS * D_DIM];
__device__ float g_bias[3 * D_DIM];

// ===========================================================================
// Helpers
// ===========================================================================
__device__ __forceinline__ uint32_t smem_u32(const void* p) {
    uint32_t a;
    asm("{ .reg .u64 t; cvta.to.shared.u64 t, %1; cvt.u32.u64 %0, t; }"
        : "=r"(a) : "l"(p));
    return a;
}
#define SW128(o) ((o) ^ (((o) >> 3) & 0x70))

#define LDSM4(r, addr) \
    asm volatile("ldmatrix.sync.aligned.m8n8.x4.shared.b16 {%0,%1,%2,%3}, [%4];" \
        : "=r"((r)[0]), "=r"((r)[1]), "=r"((r)[2]), "=r"((r)[3]) : "r"(addr))

#define LDSM4T(r, addr) \
    asm volatile("ldmatrix.sync.aligned.m8n8.x4.trans.shared.b16 {%0,%1,%2,%3}, [%4];" \
        : "=r"((r)[0]), "=r"((r)[1]), "=r"((r)[2]), "=r"((r)[3]) : "r"(addr))

#define MMA_BF16(d, a, b0_, b1_) \
    asm volatile("mma.sync.aligned.m16n8k16.row.col.f32.bf16.bf16.f32 " \
        "{%0,%1,%2,%3}, {%4,%5,%6,%7}, {%8,%9}, {%0,%1,%2,%3};" \
        : "+f"((d)[0]), "+f"((d)[1]), "+f"((d)[2]), "+f"((d)[3]) \
        : "r"((a)[0]), "r"((a)[1]), "r"((a)[2]), "r"((a)[3]), \
          "r"(b0_), "r"(b1_))

__device__ __forceinline__ void sts128(uint32_t addr, uint32_t a, uint32_t b,
                                       uint32_t c, uint32_t d) {
    asm volatile("st.shared.v4.b32 [%0], {%1,%2,%3,%4};"
                 :: "r"(addr), "r"(a), "r"(b), "r"(c), "r"(d) : "memory");
}
__device__ __forceinline__ void cvt_pair(float f0, float f1,
                                         uint32_t& hw, uint32_t& lw) {
    __nv_bfloat162 h = __floats2bfloat162_rn(f0, f1);
    float g0 = __bfloat162float(__low2bfloat16(h));
    float g1 = __bfloat162float(__high2bfloat16(h));
    __nv_bfloat162 l = __floats2bfloat162_rn(f0 - g0, f1 - g1);
    hw = *reinterpret_cast<uint32_t*>(&h);
    lw = *reinterpret_cast<uint32_t*>(&l);
}

// ===========================================================================
// Fused preconvert kernels
// ===========================================================================
__global__ __launch_bounds__(256) void cvt3_kernel(
    const float* __restrict__ s0, const float* __restrict__ s1,
    const float* __restrict__ s2,
    __nv_bfloat16* __restrict__ h, __nv_bfloat16* __restrict__ l, int n4seg) {
    const int segi = blockIdx.y;
    const float* s = (segi == 0) ? s0 : (segi == 1 ? s1 : s2);
    const int base = segi * n4seg;
    const int stride = gridDim.x * 256;
    for (int j = blockIdx.x * 256 + threadIdx.x; j < n4seg; j += stride) {
        float4 v = ((const float4*)s)[j];
        uint32_t h0, h1, l0, l1;
        cvt_pair(v.x, v.y, h0, l0);
        cvt_pair(v.z, v.w, h1, l1);
        ((uint2*)h)[base + j] = make_uint2(h0, h1);
        ((uint2*)l)[base + j] = make_uint2(l0, l1);
    }
}

__global__ __launch_bounds__(256) void cvt4_kernel(
    const float* __restrict__ s0, const float* __restrict__ s1,
    const float* __restrict__ s2, const float* __restrict__ s3,
    __nv_bfloat16* __restrict__ h, __nv_bfloat16* __restrict__ l, int n4seg) {
    const int segi = blockIdx.y;
    const float* s = (segi == 0) ? s0 : (segi == 1 ? s1 : (segi == 2 ? s2 : s3));
    const int base = segi * n4seg;
    const int stride = gridDim.x * 256;
    for (int j = blockIdx.x * 256 + threadIdx.x; j < n4seg; j += stride) {
        float4 v = ((const float4*)s)[j];
        uint32_t h0, h1, l0, l1;
        cvt_pair(v.x, v.y, h0, l0);
        cvt_pair(v.z, v.w, h1, l1);
        ((uint2*)h)[base + j] = make_uint2(h0, h1);
        ((uint2*)l)[base + j] = make_uint2(l0, l1);
    }
}

// ===========================================================================
// Split-bf16 warp-MMA GEMM v5: term-major MMA issue order (16 independent
// accumulators between reuses of any d) to break the HMMA RAW chain.
// ===========================================================================
#define NSTAGE 3
#define G_STAGE 32768
#define GEMM_SMEM (NSTAGE * G_STAGE)   // 98304

__global__ __launch_bounds__(256, 2) void gemm_tc_kernel(
    const __nv_bfloat16* __restrict__ Ah_, const __nv_bfloat16* __restrict__ Al_,
    const __nv_bfloat16* __restrict__ Wh_, const __nv_bfloat16* __restrict__ Wl_,
    const float* __restrict__ bias, float* __restrict__ C,
    __nv_bfloat16* __restrict__ qh, __nv_bfloat16* __restrict__ ql,
    __nv_bfloat16* __restrict__ kh, __nv_bfloat16* __restrict__ kl,
    __nv_bfloat16* __restrict__ vh, __nv_bfloat16* __restrict__ vl) {
    extern __shared__ char smem[];
    const uint32_t sb = smem_u32(smem);

    const int tid = threadIdx.x;
    const int wid = tid >> 5;
    const int lane = tid & 31;
    const int wm = wid >> 2;
    const int wn = wid & 3;
    const int seg = blockIdx.y >> 6;
    const int row0 = blockIdx.y * 128;
    const int wrow0 = seg * 1024 + blockIdx.x * 128;
    const int col0 = blockIdx.x * 128;

    const int grp = lane >> 3, rin = lane & 7;
    const int a_mrow = ((grp & 1) << 3) + rin;
    const int a_kb   = (grp >> 1) << 4;
    const int b_nrow = ((grp >> 1) << 3) + rin;
    const int b_kb   = (grp & 1) << 4;

    const int rbase = tid >> 2;
    const int cseg = tid & 3;
    const size_t offA0 = (size_t)(row0 + rbase) * 1024 + cseg * 8;
    const size_t offA1 = offA0 + (size_t)64 * 1024;
    const size_t offW0 = (size_t)(wrow0 + rbase) * 1024 + cseg * 8;
    const size_t offW1 = offW0 + (size_t)64 * 1024;
    const uint32_t s0 = SW128(rbase * 128 + cseg * 16);
    const uint32_t s1 = SW128((64 + rbase) * 128 + cseg * 16);
    const uint32_t s2 = SW128(rbase * 128 + 64 + cseg * 16);
    const uint32_t s3 = SW128((64 + rbase) * 128 + 64 + cseg * 16);

    auto issue_stage = [&](int s) {
        const int kb = s * 32;
        const uint32_t dst = sb + (s % NSTAGE) * G_STAGE;
        asm volatile("cp.async.cg.shared.global [%0], [%1], 16;" :: "r"(dst + s0), "l"(Ah_ + offA0 + kb));
        asm volatile("cp.async.cg.shared.global [%0], [%1], 16;" :: "r"(dst + s1), "l"(Ah_ + offA1 + kb));
        asm volatile("cp.async.cg.shared.global [%0], [%1], 16;" :: "r"(dst + s2), "l"(Al_ + offA0 + kb));
        asm volatile("cp.async.cg.shared.global [%0], [%1], 16;" :: "r"(dst + s3), "l"(Al_ + offA1 + kb));
        asm volatile("cp.async.cg.shared.global [%0], [%1], 16;" :: "r"(dst + 16384 + s0), "l"(Wh_ + offW0 + kb));
        asm volatile("cp.async.cg.shared.global [%0], [%1], 16;" :: "r"(dst + 16384 + s1), "l"(Wh_ + offW1 + kb));
        asm volatile("cp.async.cg.shared.global [%0], [%1], 16;" :: "r"(dst + 16384 + s2), "l"(Wl_ + offW0 + kb));
        asm volatile("cp.async.cg.shared.global [%0], [%1], 16;" :: "r"(dst + 16384 + s3), "l"(Wl_ + offW1 + kb));
        asm volatile("cp.async.commit_group;" ::: "memory");
    };

    float acc[4][4][4];
    #pragma unroll
    for (int i = 0; i < 4; i++)
        #pragma unroll
        for (int j = 0; j < 4; j++)
            #pragma unroll
            for (int k = 0; k < 4; k++) acc[i][j][k] = 0.0f;

    issue_stage(0);
    issue_stage(1);

    #pragma unroll 1
    for (int s = 0; s < 32; s++) {
        asm volatile("cp.async.wait_group %0;" :: "n"(NSTAGE - 2) : "memory");
        __syncthreads();
        if (s + 2 < 32) issue_stage(s + 2);
        else asm volatile("cp.async.commit_group;" ::: "memory");

        const uint32_t AsB = sb + (s % NSTAGE) * G_STAGE;
        const uint32_t BsB = AsB + 16384;
        #pragma unroll
        for (int ks = 0; ks < 2; ks++) {
            uint32_t ah[4][4], al[4][4], bh[2][4], bl[2][4];
            #pragma unroll
            for (int mt = 0; mt < 4; mt++) {
                int row = wm * 64 + mt * 16 + a_mrow;
                uint32_t off = row * 128 + ks * 32 + a_kb;
                LDSM4(ah[mt], AsB + SW128(off));
                LDSM4(al[mt], AsB + SW128(off + 64));
            }
            #pragma unroll
            for (int np = 0; np < 2; np++) {
                int row = wn * 32 + np * 16 + b_nrow;
                uint32_t off = row * 128 + ks * 32 + b_kb;
                LDSM4(bh[np], BsB + SW128(off));
                LDSM4(bl[np], BsB + SW128(off + 64));
            }
            // Term-major issue: 16 independent accumulators between d reuses.
            #pragma unroll
            for (int mt = 0; mt < 4; mt++)
                #pragma unroll
                for (int np = 0; np < 2; np++)
                    #pragma unroll
                    for (int sub = 0; sub < 2; sub++)
                        MMA_BF16(acc[mt][np * 2 + sub], ah[mt],
                                 bh[np][sub * 2], bh[np][sub * 2 + 1]);
            #pragma unroll
            for (int mt = 0; mt < 4; mt++)
                #pragma unroll
                for (int np = 0; np < 2; np++)
                    #pragma unroll
                    for (int sub = 0; sub < 2; sub++)
                        MMA_BF16(acc[mt][np * 2 + sub], al[mt],
                                 bh[np][sub * 2], bh[np][sub * 2 + 1]);
            #pragma unroll
            for (int mt = 0; mt < 4; mt++)
                #pragma unroll
                for (int np = 0; np < 2; np++)
                    #pragma unroll
                    for (int sub = 0; sub < 2; sub++)
                        MMA_BF16(acc[mt][np * 2 + sub], ah[mt],
                                 bl[np][sub * 2], bl[np][sub * 2 + 1]);
        }
    }

    if (C != nullptr) {
        #pragma unroll
        for (int mt = 0; mt < 4; mt++) {
            int rg = row0 + wm * 64 + mt * 16 + (lane >> 2);
            #pragma unroll
            for (int nt = 0; nt < 4; nt++) {
                int cg = col0 + wn * 32 + nt * 8 + (lane & 3) * 2;
                float b0 = __ldg(&bias[cg]), b1 = __ldg(&bias[cg + 1]);
                float2 v0 = make_float2(acc[mt][nt][0] + b0, acc[mt][nt][1] + b1);
                float2 v1 = make_float2(acc[mt][nt][2] + b0, acc[mt][nt][3] + b1);
                *(float2*)&C[(size_t)rg * 1024 + cg] = v0;
                *(float2*)&C[(size_t)(rg + 8) * 1024 + cg] = v1;
            }
        }
    } else {
        __nv_bfloat16* Ph = seg == 0 ? qh : (seg == 1 ? kh : vh);
        __nv_bfloat16* Pl = seg == 0 ? ql : (seg == 1 ? kl : vl);
        const float scale = (seg == 0) ? 0.125f : 1.0f;
        const int ry = (blockIdx.y & 63) * 128;
        #pragma unroll
        for (int mt = 0; mt < 4; mt++) {
            int rg = ry + wm * 64 + mt * 16 + (lane >> 2);
            int t = rg >> 3, bb = rg & 7;
            #pragma unroll
            for (int nt = 0; nt < 4; nt++) {
                int cg = col0 + wn * 32 + nt * 8 + (lane & 3) * 2;
                int hh = cg >> 6, hd = cg & 63;
                size_t pb = ((size_t)(bb * 16 + hh)) * 65536 + (size_t)t * 64 + hd;
                float b0 = __ldg(&bias[seg * 1024 + cg]);
                float b1 = __ldg(&bias[seg * 1024 + cg + 1]);
                uint32_t hw, lw;
                cvt_pair((acc[mt][nt][0] + b0) * scale,
                         (acc[mt][nt][1] + b1) * scale, hw, lw);
                *(uint32_t*)&Ph[pb] = hw;
                *(uint32_t*)&Pl[pb] = lw;
                cvt_pair((acc[mt][nt][2] + b0) * scale,
                         (acc[mt][nt][3] + b1) * scale, hw, lw);
                *(uint32_t*)&Ph[pb + 64] = hw;
                *(uint32_t*)&Pl[pb + 64] = lw;
            }
        }
    }
}

// ===========================================================================
// Tensor-core flash attention with cp.async double-buffered K/V.
// MMA terms interleaved over sub to shorten RAW chains on accumulators.
// ===========================================================================
#define ATTN_SMEM 163840

__global__ __launch_bounds__(256, 1) void attn_tc_kernel(
    const __nv_bfloat16* __restrict__ qh, const __nv_bfloat16* __restrict__ ql,
    const __nv_bfloat16* __restrict__ kh, const __nv_bfloat16* __restrict__ kl,
    const __nv_bfloat16* __restrict__ vh, const __nv_bfloat16* __restrict__ vl,
    __nv_bfloat16* __restrict__ ch, __nv_bfloat16* __restrict__ cl) {
    extern __shared__ char smem[];
    const uint32_t sb = smem_u32(smem);
    const int tid = threadIdx.x, wid = tid >> 5, lane = tid & 31;
    const int grp = lane >> 3, rin = lane & 7;
    const int head = blockIdx.y;
    const int q0 = blockIdx.x * 128;
    const size_t hbase = (size_t)head * 65536;

    enum { QH = 0, QL = 16384, STAGE0 = 32768, STAGE_SZ = 65536 };
    enum { KHo = 0, KLo = 16384, VHo = 32768, VLo = 49152 };

    {
        const uint4* sh = (const uint4*)(qh + hbase + (size_t)q0 * 64);
        const uint4* sl = (const uint4*)(ql + hbase + (size_t)q0 * 64);
        #pragma unroll
        for (int i = 0; i < 4; i++) {
            int c = tid + i * 256;
            uint32_t d = SW128(c * 16);
            uint4 a = sh[c]; sts128(sb + QH + d, a.x, a.y, a.z, a.w);
            uint4 b = sl[c]; sts128(sb + QL + d, b.x, b.y, b.z, b.w);
        }
    }

    auto issue_kv = [&](int kt) {
        const uint32_t st = sb + STAGE0 + (kt & 1) * STAGE_SZ;
        const size_t tb = hbase + (size_t)kt * 8192;
        const __nv_bfloat16* pkh = kh + tb;
        const __nv_bfloat16* pkl = kl + tb;
        const __nv_bfloat16* pvh = vh + tb;
        const __nv_bfloat16* pvl = vl + tb;
        #pragma unroll
        for (int i = 0; i < 4; i++) {
            int c = tid + i * 256;
            uint32_t d = SW128(c * 16);
            asm volatile("cp.async.cg.shared.global [%0], [%1], 16;" :: "r"(st + KHo + d), "l"(pkh + c * 8));
            asm volatile("cp.async.cg.shared.global [%0], [%1], 16;" :: "r"(st + KLo + d), "l"(pkl + c * 8));
            asm volatile("cp.async.cg.shared.global [%0], [%1], 16;" :: "r"(st + VHo + d), "l"(pvh + c * 8));
            asm volatile("cp.async.cg.shared.global [%0], [%1], 16;" :: "r"(st + VLo + d), "l"(pvl + c * 8));
        }
        asm volatile("cp.async.commit_group;" ::: "memory");
    };

    issue_kv(0);
    __syncthreads();

    const int a_row = wid * 16 + ((grp & 1) << 3) + rin;
    const int a_kb = (grp >> 1) << 4;
    uint32_t qfh[4][4], qfl[4][4];
    #pragma unroll
    for (int ks = 0; ks < 4; ks++) {
        uint32_t off = a_row * 128 + ks * 32 + a_kb;
        LDSM4(qfh[ks], sb + QH + SW128(off));
        LDSM4(qfl[ks], sb + QL + SW128(off));
    }

    const int b_rowb = ((grp >> 1) << 3) + rin;
    const int b_kb = (grp & 1) << 4;
    const int v_rowb = ((grp & 1) << 3) + rin;
    const int v_cb = (grp >> 1) << 4;

    float sc[16][4];
    float oacc[8][4];
    #pragma unroll
    for (int i = 0; i < 8; i++)
        #pragma unroll
        for (int j = 0; j < 4; j++) oacc[i][j] = 0.0f;
    float m1 = -INFINITY, m2 = -INFINITY, l1 = 0.0f, l2 = 0.0f;

    #pragma unroll 1
    for (int kt = 0; kt < 8; kt++) {
        __syncthreads();
        if (kt < 7) {
            issue_kv(kt + 1);
            asm volatile("cp.async.wait_group 1;" ::: "memory");
        } else {
            asm volatile("cp.async.wait_group 0;" ::: "memory");
        }
        __syncthreads();

        const uint32_t st = sb + STAGE0 + (kt & 1) * STAGE_SZ;

        #pragma unroll
        for (int j = 0; j < 16; j++)
            #pragma unroll
            for (int c = 0; c < 4; c++) sc[j][c] = 0.0f;
        #pragma unroll
        for (int ks = 0; ks < 4; ks++) {
            #pragma unroll
            for (int nb = 0; nb < 8; nb++) {
                uint32_t kfh[4], kfl[4];
                uint32_t off = (nb * 16 + b_rowb) * 128 + ks * 32 + b_kb;
                LDSM4(kfh, st + KHo + SW128(off));
                LDSM4(kfl, st + KLo + SW128(off));
                // term-major over sub: chain distance 2 on each sc
                #pragma unroll
                for (int sub = 0; sub < 2; sub++)
                    MMA_BF16(sc[nb * 2 + sub], qfh[ks], kfh[sub * 2], kfh[sub * 2 + 1]);
                #pragma unroll
                for (int sub = 0; sub < 2; sub++)
                    MMA_BF16(sc[nb * 2 + sub], qfl[ks], kfh[sub * 2], kfh[sub * 2 + 1]);
                #pragma unroll
                for (int sub = 0; sub < 2; sub++)
                    MMA_BF16(sc[nb * 2 + sub], qfh[ks], kfl[sub * 2], kfl[sub * 2 + 1]);
            }
        }

        float tm1 = -INFINITY, tm2 = -INFINITY;
        #pragma unroll
        for (int j = 0; j < 16; j++) {
            tm1 = fmaxf(tm1, fmaxf(sc[j][0], sc[j][1]));
            tm2 = fmaxf(tm2, fmaxf(sc[j][2], sc[j][3]));
        }
        tm1 = fmaxf(tm1, __shfl_xor_sync(0xffffffffu, tm1, 1));
        tm1 = fmaxf(tm1, __shfl_xor_sync(0xffffffffu, tm1, 2));
        tm2 = fmaxf(tm2, __shfl_xor_sync(0xffffffffu, tm2, 1));
        tm2 = fmaxf(tm2, __shfl_xor_sync(0xffffffffu, tm2, 2));

        float mn1 = fmaxf(m1, tm1), mn2 = fmaxf(m2, tm2);
        float al1 = __expf(m1 - mn1), al2 = __expf(m2 - mn2);
        m1 = mn1; m2 = mn2;

        float s1 = 0.0f, s2 = 0.0f;
        #pragma unroll
        for (int j = 0; j < 16; j++) {
            sc[j][0] = __expf(sc[j][0] - mn1);
            sc[j][1] = __expf(sc[j][1] - mn1);
            s1 += sc[j][0] + sc[j][1];
            sc[j][2] = __expf(sc[j][2] - mn2);
            sc[j][3] = __expf(sc[j][3] - mn2);
            s2 += sc[j][2] + sc[j][3];
        }
        s1 += __shfl_xor_sync(0xffffffffu, s1, 1);
        s1 += __shfl_xor_sync(0xffffffffu, s1, 2);
        s2 += __shfl_xor_sync(0xffffffffu, s2, 1);
        s2 += __shfl_xor_sync(0xffffffffu, s2, 2);
        l1 = l1 * al1 + s1;
        l2 = l2 * al2 + s2;
        #pragma unroll
        for (int nb = 0; nb < 8; nb++) {
            oacc[nb][0] *= al1; oacc[nb][1] *= al1;
            oacc[nb][2] *= al2; oacc[nb][3] *= al2;
        }

        #pragma unroll
        for (int ksv = 0; ksv < 8; ksv++) {
            uint32_t pah[4], pal[4];
            const int j0 = 2 * ksv, j1 = j0 + 1;
            cvt_pair(sc[j0][0], sc[j0][1], pah[0], pal[0]);
            cvt_pair(sc[j0][2], sc[j0][3], pah[1], pal[1]);
            cvt_pair(sc[j1][0], sc[j1][1], pah[2], pal[2]);
            cvt_pair(sc[j1][2], sc[j1][3], pah[3], pal[3]);
            #pragma unroll
            for (int nv = 0; nv < 4; nv++) {
                uint32_t vfh[4], vfl[4];
                uint32_t off = (ksv * 16 + v_rowb) * 128 + nv * 32 + v_cb;
                LDSM4T(vfh, st + VHo + SW128(off));
                LDSM4T(vfl, st + VLo + SW128(off));
                // term-major over sub
                #pragma unroll
                for (int sub = 0; sub < 2; sub++)
                    MMA_BF16(oacc[nv * 2 + sub], pah, vfh[sub * 2], vfh[sub * 2 + 1]);
                #pragma unroll
                for (int sub = 0; sub < 2; sub++)
                    MMA_BF16(oacc[nv * 2 + sub], pal, vfh[sub * 2], vfh[sub * 2 + 1]);
                #pragma unroll
                for (int sub = 0; sub < 2; sub++)
                    MMA_BF16(oacc[nv * 2 + sub], pah, vfl[sub * 2], vfl[sub * 2 + 1]);
            }
        }
    }

    const float inv1 = 1.0f / l1, inv2 = 1.0f / l2;
    const int t1 = q0 + wid * 16 + (lane >> 2);
    const int bb = head >> 4, hh = head & 15;
    const int colb = hh * 64 + 2 * (lane & 3);
    #pragma unroll
    for (int nb = 0; nb < 8; nb++) {
        int col = colb + nb * 8;
        size_t o1 = ((size_t)t1 * 8 + bb) * 1024 + col;
        uint32_t hw, lw;
        cvt_pair(oacc[nb][0] * inv1, oacc[nb][1] * inv1, hw, lw);
        *(uint32_t*)&ch[o1] = hw;
        *(uint32_t*)&cl[o1] = lw;
        cvt_pair(oacc[nb][2] * inv2, oacc[nb][3] * inv2, hw, lw);
        *(uint32_t*)&ch[o1 + 65536] = hw;
        *(uint32_t*)&cl[o1 + 65536] = lw;
    }
}

// ===========================================================================
// Launch
// ===========================================================================
extern "C" void kernel_launch(void* const* d_in, const int* in_sizes, int n_in,
                              void* d_out, int out_size) {
    const float* query = (const float*)d_in[0];
    const float* key   = (const float*)d_in[1];
    const float* value = (const float*)d_in[2];
    const float* Wq = (const float*)d_in[3];
    const float* bq = (const float*)d_in[4];
    const float* Wk = (const float*)d_in[5];
    const float* bk = (const float*)d_in[6];
    const float* Wv = (const float*)d_in[7];
    const float* bv = (const float*)d_in[8];
    const float* Wo = (const float*)d_in[9];
    const float* bo = (const float*)d_in[10];
    float* out = (float*)d_out;

    __nv_bfloat16 *pqh, *pql, *pkh, *pkl, *pvh, *pvl;
    __nv_bfloat16 *xh, *xl, *wh, *wl, *ch, *cl;
    float* biasb;
    cudaGetSymbolAddress((void**)&pqh, g_qh);
    cudaGetSymbolAddress((void**)&pql, g_ql);
    cudaGetSymbolAddress((void**)&pkh, g_kh);
    cudaGetSymbolAddress((void**)&pkl, g_kl);
    cudaGetSymbolAddress((void**)&pvh, g_vh);
    cudaGetSymbolAddress((void**)&pvl, g_vl);
    cudaGetSymbolAddress((void**)&xh, g_xh);
    cudaGetSymbolAddress((void**)&xl, g_xl);
    cudaGetSymbolAddress((void**)&wh, g_wh);
    cudaGetSymbolAddress((void**)&wl, g_wl);
    cudaGetSymbolAddress((void**)&ch, g_ch);
    cudaGetSymbolAddress((void**)&cl, g_cl);
    cudaGetSymbolAddress((void**)&biasb, g_bias);

    cudaFuncSetAttribute(gemm_tc_kernel,
                         cudaFuncAttributeMaxDynamicSharedMemorySize, GEMM_SMEM);
    cudaFuncSetAttribute(attn_tc_kernel,
                         cudaFuncAttributeMaxDynamicSharedMemorySize, ATTN_SMEM);

    const int n4_in = M_ROWS * D_DIM / 4;
    const int n4_w  = D_DIM * D_DIM / 4;
    const int W_OFF  = D_DIM * D_DIM;

    cvt3_kernel<<<dim3(1024, 3), 256>>>(query, key, value, xh, xl, n4_in);
    cvt4_kernel<<<dim3(256, 4), 256>>>(Wq, Wk, Wv, Wo, wh, wl, n4_w);
    cudaMemcpyAsync(biasb, bq, D_DIM * sizeof(float), cudaMemcpyDeviceToDevice);
    cudaMemcpyAsync(biasb + D_DIM, bk, D_DIM * sizeof(float), cudaMemcpyDeviceToDevice);
    cudaMemcpyAsync(biasb + 2 * D_DIM, bv, D_DIM * sizeof(float), cudaMemcpyDeviceToDevice);

    dim3 qkv_grid(D_DIM / 128, 3 * M_ROWS / 128);
    gemm_tc_kernel<<<qkv_grid, 256, GEMM_SMEM>>>(xh, xl, wh, wl, biasb, nullptr,
                                                 pqh, pql, pkh, pkl, pvh, pvl);

    dim3 attn_grid(T_DIM / 128, B_DIM * H_DIM);
    attn_tc_kernel<<<attn_grid, 256, ATTN_SMEM>>>(pqh, pql, pkh, pkl,
                                                  pvh, pvl, ch, cl);

    dim3 o_grid(D_DIM / 128, M_ROWS / 128);
    gemm_tc_kernel<<<o_grid, 256, GEMM_SMEM>>>(ch, cl, wh + 3 * W_OFF, wl + 3 * W_OFF,
                                               bo, out,
                                               pqh, pql, pkh, pkl, pvh, pvl);
}

// round 16
// speedup vs baseline: 1.4153x; 1.2019x over previous
#include <cuda_runtime.h>
#include <cuda_bf16.h>
#include <cuda_fp16.h>
#include <stdint.h>
#include <math.h>

// Problem constants
#define T_DIM 1024
#define B_DIM 8
#define D_DIM 1024
#define H_DIM 16
#define HD_DIM 64
#define M_ROWS (T_DIM * B_DIM)        // 8192

// Scratch (no cudaMalloc allowed)
#define PLANE_ELEMS (128 * 1024 * 64)
__device__ __nv_bfloat16 g_qh[PLANE_ELEMS], g_ql[PLANE_ELEMS];   // attn planes (bf16)
__device__ __nv_bfloat16 g_kh[PLANE_ELEMS], g_kl[PLANE_ELEMS];
__device__ __nv_bfloat16 g_vh[PLANE_ELEMS], g_vl[PLANE_ELEMS];
__device__ __half g_xh[3 * M_ROWS * D_DIM], g_xl[3 * M_ROWS * D_DIM];  // fp16 input planes
__device__ __half g_wh[4 * D_DIM * D_DIM];                             // fp16 weights (rounded)
__device__ __half g_ch[M_ROWS * D_DIM], g_cl[M_ROWS * D_DIM];          // fp16 ctx planes
__device__ float g_bias[3 * D_DIM];

// ===========================================================================
// Helpers
// ===========================================================================
__device__ __forceinline__ uint32_t smem_u32(const void* p) {
    uint32_t a;
    asm("{ .reg .u64 t; cvta.to.shared.u64 t, %1; cvt.u32.u64 %0, t; }"
        : "=r"(a) : "l"(p));
    return a;
}
#define SW128(o) ((o) ^ (((o) >> 3) & 0x70))

#define LDSM4(r, addr) \
    asm volatile("ldmatrix.sync.aligned.m8n8.x4.shared.b16 {%0,%1,%2,%3}, [%4];" \
        : "=r"((r)[0]), "=r"((r)[1]), "=r"((r)[2]), "=r"((r)[3]) : "r"(addr))

#define LDSM4T(r, addr) \
    asm volatile("ldmatrix.sync.aligned.m8n8.x4.trans.shared.b16 {%0,%1,%2,%3}, [%4];" \
        : "=r"((r)[0]), "=r"((r)[1]), "=r"((r)[2]), "=r"((r)[3]) : "r"(addr))

#define MMA_BF16(d, a, b0_, b1_) \
    asm volatile("mma.sync.aligned.m16n8k16.row.col.f32.bf16.bf16.f32 " \
        "{%0,%1,%2,%3}, {%4,%5,%6,%7}, {%8,%9}, {%0,%1,%2,%3};" \
        : "+f"((d)[0]), "+f"((d)[1]), "+f"((d)[2]), "+f"((d)[3]) \
        : "r"((a)[0]), "r"((a)[1]), "r"((a)[2]), "r"((a)[3]), \
          "r"(b0_), "r"(b1_))

#define MMA_FP16(d, a, b0_, b1_) \
    asm volatile("mma.sync.aligned.m16n8k16.row.col.f32.f16.f16.f32 " \
        "{%0,%1,%2,%3}, {%4,%5,%6,%7}, {%8,%9}, {%0,%1,%2,%3};" \
        : "+f"((d)[0]), "+f"((d)[1]), "+f"((d)[2]), "+f"((d)[3]) \
        : "r"((a)[0]), "r"((a)[1]), "r"((a)[2]), "r"((a)[3]), \
          "r"(b0_), "r"(b1_))

__device__ __forceinline__ void sts128(uint32_t addr, uint32_t a, uint32_t b,
                                       uint32_t c, uint32_t d) {
    asm volatile("st.shared.v4.b32 [%0], {%1,%2,%3,%4};"
                 :: "r"(addr), "r"(a), "r"(b), "r"(c), "r"(d) : "memory");
}
// split fp32 pair -> (hi bf16x2, lo bf16x2)
__device__ __forceinline__ void cvt_pair(float f0, float f1,
                                         uint32_t& hw, uint32_t& lw) {
    __nv_bfloat162 h = __floats2bfloat162_rn(f0, f1);
    float g0 = __bfloat162float(__low2bfloat16(h));
    float g1 = __bfloat162float(__high2bfloat16(h));
    __nv_bfloat162 l = __floats2bfloat162_rn(f0 - g0, f1 - g1);
    hw = *reinterpret_cast<uint32_t*>(&h);
    lw = *reinterpret_cast<uint32_t*>(&l);
}
// split fp32 pair -> (hi fp16x2, lo fp16x2)
__device__ __forceinline__ void cvt_pair_h(float f0, float f1,
                                           uint32_t& hw, uint32_t& lw) {
    __half2 h = __floats2half2_rn(f0, f1);
    float g0 = __half2float(__low2half(h));
    float g1 = __half2float(__high2half(h));
    __half2 l = __floats2half2_rn(f0 - g0, f1 - g1);
    hw = *reinterpret_cast<uint32_t*>(&h);
    lw = *reinterpret_cast<uint32_t*>(&l);
}

// ===========================================================================
// Preconvert: inputs -> fp16 hi/lo planes; weights -> single rounded fp16
// ===========================================================================
__global__ __launch_bounds__(256) void cvt3_kernel(
    const float* __restrict__ s0, const float* __restrict__ s1,
    const float* __restrict__ s2,
    __half* __restrict__ h, __half* __restrict__ l, int n4seg) {
    const int segi = blockIdx.y;
    const float* s = (segi == 0) ? s0 : (segi == 1 ? s1 : s2);
    const int base = segi * n4seg;
    const int stride = gridDim.x * 256;
    for (int j = blockIdx.x * 256 + threadIdx.x; j < n4seg; j += stride) {
        float4 v = ((const float4*)s)[j];
        uint32_t h0, h1, l0, l1;
        cvt_pair_h(v.x, v.y, h0, l0);
        cvt_pair_h(v.z, v.w, h1, l1);
        ((uint2*)h)[base + j] = make_uint2(h0, h1);
        ((uint2*)l)[base + j] = make_uint2(l0, l1);
    }
}

__global__ __launch_bounds__(256) void cvtw_kernel(
    const float* __restrict__ s0, const float* __restrict__ s1,
    const float* __restrict__ s2, const float* __restrict__ s3,
    __half* __restrict__ w, int n4seg) {
    const int segi = blockIdx.y;
    const float* s = (segi == 0) ? s0 : (segi == 1 ? s1 : (segi == 2 ? s2 : s3));
    const int base = segi * n4seg;
    const int stride = gridDim.x * 256;
    for (int j = blockIdx.x * 256 + threadIdx.x; j < n4seg; j += stride) {
        float4 v = ((const float4*)s)[j];
        __half2 a = __floats2half2_rn(v.x, v.y);
        __half2 b = __floats2half2_rn(v.z, v.w);
        ((uint2*)w)[base + j] = make_uint2(*reinterpret_cast<uint32_t*>(&a),
                                           *reinterpret_cast<uint32_t*>(&b));
    }
}

// ===========================================================================
// fp16 2-term warp-MMA GEMM: out = X @ W^T + bias.
// X split exactly into fp16 hi/lo planes; W rounded to one fp16 plane.
// Terms per step: Xh*Wh + Xl*Wh  (2 MMAs; residual 2^-22 from X only,
// W rounding error ~2.8e-4 RMS).
// ===========================================================================
#define NSTAGE 3
#define G_STAGE 32768
#define GEMM_SMEM (NSTAGE * G_STAGE)   // 98304

__global__ __launch_bounds__(256, 2) void gemm_tc_kernel(
    const __half* __restrict__ Ah_, const __half* __restrict__ Al_,
    const __half* __restrict__ Wh_,
    const float* __restrict__ bias, float* __restrict__ C,
    __nv_bfloat16* __restrict__ qh, __nv_bfloat16* __restrict__ ql,
    __nv_bfloat16* __restrict__ kh, __nv_bfloat16* __restrict__ kl,
    __nv_bfloat16* __restrict__ vh, __nv_bfloat16* __restrict__ vl) {
    extern __shared__ char smem[];
    const uint32_t sb = smem_u32(smem);

    const int tid = threadIdx.x;
    const int wid = tid >> 5;
    const int lane = tid & 31;
    const int wm = wid >> 2;
    const int wn = wid & 3;
    const int seg = blockIdx.y >> 6;
    const int row0 = blockIdx.y * 128;
    const int wrow0 = seg * 1024 + blockIdx.x * 128;
    const int col0 = blockIdx.x * 128;

    const int grp = lane >> 3, rin = lane & 7;
    const int a_mrow = ((grp & 1) << 3) + rin;
    const int a_kb   = (grp >> 1) << 4;
    const int b_nrow = ((grp >> 1) << 3) + rin;
    const int b_kb   = (grp & 1) << 4;

    const int rbase = tid >> 2;
    const int cseg = tid & 3;
    const size_t offA0 = (size_t)(row0 + rbase) * 1024 + cseg * 8;
    const size_t offA1 = offA0 + (size_t)64 * 1024;
    const size_t offW0 = (size_t)(wrow0 + rbase) * 1024 + cseg * 8;
    const size_t offW1 = offW0 + (size_t)64 * 1024;
    const uint32_t s0 = SW128(rbase * 128 + cseg * 16);
    const uint32_t s1 = SW128((64 + rbase) * 128 + cseg * 16);
    const uint32_t s2 = SW128(rbase * 128 + 64 + cseg * 16);
    const uint32_t s3 = SW128((64 + rbase) * 128 + 64 + cseg * 16);

    auto issue_stage = [&](int s) {
        const int kb = s * 32;
        const uint32_t dst = sb + (s % NSTAGE) * G_STAGE;
        asm volatile("cp.async.cg.shared.global [%0], [%1], 16;" :: "r"(dst + s0), "l"(Ah_ + offA0 + kb));
        asm volatile("cp.async.cg.shared.global [%0], [%1], 16;" :: "r"(dst + s1), "l"(Ah_ + offA1 + kb));
        asm volatile("cp.async.cg.shared.global [%0], [%1], 16;" :: "r"(dst + s2), "l"(Al_ + offA0 + kb));
        asm volatile("cp.async.cg.shared.global [%0], [%1], 16;" :: "r"(dst + s3), "l"(Al_ + offA1 + kb));
        asm volatile("cp.async.cg.shared.global [%0], [%1], 16;" :: "r"(dst + 16384 + s0), "l"(Wh_ + offW0 + kb));
        asm volatile("cp.async.cg.shared.global [%0], [%1], 16;" :: "r"(dst + 16384 + s1), "l"(Wh_ + offW1 + kb));
        asm volatile("cp.async.commit_group;" ::: "memory");
    };

    float acc[4][4][4];
    #pragma unroll
    for (int i = 0; i < 4; i++)
        #pragma unroll
        for (int j = 0; j < 4; j++)
            #pragma unroll
            for (int k = 0; k < 4; k++) acc[i][j][k] = 0.0f;

    issue_stage(0);
    issue_stage(1);

    #pragma unroll 1
    for (int s = 0; s < 32; s++) {
        asm volatile("cp.async.wait_group %0;" :: "n"(NSTAGE - 2) : "memory");
        __syncthreads();
        if (s + 2 < 32) issue_stage(s + 2);
        else asm volatile("cp.async.commit_group;" ::: "memory");

        const uint32_t AsB = sb + (s % NSTAGE) * G_STAGE;
        const uint32_t BsB = AsB + 16384;
        #pragma unroll
        for (int ks = 0; ks < 2; ks++) {
            uint32_t ah[4][4], al[4][4], bh[2][4];
            #pragma unroll
            for (int mt = 0; mt < 4; mt++) {
                int row = wm * 64 + mt * 16 + a_mrow;
                uint32_t off = row * 128 + ks * 32 + a_kb;
                LDSM4(ah[mt], AsB + SW128(off));
                LDSM4(al[mt], AsB + SW128(off + 64));
            }
            #pragma unroll
            for (int np = 0; np < 2; np++) {
                int row = wn * 32 + np * 16 + b_nrow;
                uint32_t off = row * 128 + ks * 32 + b_kb;
                LDSM4(bh[np], BsB + SW128(off));
            }
            // 2 terms: Xh*Wh then Xl*Wh (term-major, 16 indep accums apart)
            #pragma unroll
            for (int mt = 0; mt < 4; mt++)
                #pragma unroll
                for (int np = 0; np < 2; np++)
                    #pragma unroll
                    for (int sub = 0; sub < 2; sub++)
                        MMA_FP16(acc[mt][np * 2 + sub], ah[mt],
                                 bh[np][sub * 2], bh[np][sub * 2 + 1]);
            #pragma unroll
            for (int mt = 0; mt < 4; mt++)
                #pragma unroll
                for (int np = 0; np < 2; np++)
                    #pragma unroll
                    for (int sub = 0; sub < 2; sub++)
                        MMA_FP16(acc[mt][np * 2 + sub], al[mt],
                                 bh[np][sub * 2], bh[np][sub * 2 + 1]);
        }
    }

    if (C != nullptr) {
        #pragma unroll
        for (int mt = 0; mt < 4; mt++) {
            int rg = row0 + wm * 64 + mt * 16 + (lane >> 2);
            #pragma unroll
            for (int nt = 0; nt < 4; nt++) {
                int cg = col0 + wn * 32 + nt * 8 + (lane & 3) * 2;
                float b0 = __ldg(&bias[cg]), b1 = __ldg(&bias[cg + 1]);
                float2 v0 = make_float2(acc[mt][nt][0] + b0, acc[mt][nt][1] + b1);
                float2 v1 = make_float2(acc[mt][nt][2] + b0, acc[mt][nt][3] + b1);
                *(float2*)&C[(size_t)rg * 1024 + cg] = v0;
                *(float2*)&C[(size_t)(rg + 8) * 1024 + cg] = v1;
            }
        }
    } else {
        __nv_bfloat16* Ph = seg == 0 ? qh : (seg == 1 ? kh : vh);
        __nv_bfloat16* Pl = seg == 0 ? ql : (seg == 1 ? kl : vl);
        const float scale = (seg == 0) ? 0.125f : 1.0f;
        const int ry = (blockIdx.y & 63) * 128;
        #pragma unroll
        for (int mt = 0; mt < 4; mt++) {
            int rg = ry + wm * 64 + mt * 16 + (lane >> 2);
            int t = rg >> 3, bb = rg & 7;
            #pragma unroll
            for (int nt = 0; nt < 4; nt++) {
                int cg = col0 + wn * 32 + nt * 8 + (lane & 3) * 2;
                int hh = cg >> 6, hd = cg & 63;
                size_t pb = ((size_t)(bb * 16 + hh)) * 65536 + (size_t)t * 64 + hd;
                float b0 = __ldg(&bias[seg * 1024 + cg]);
                float b1 = __ldg(&bias[seg * 1024 + cg + 1]);
                uint32_t hw, lw;
                cvt_pair((acc[mt][nt][0] + b0) * scale,
                         (acc[mt][nt][1] + b1) * scale, hw, lw);
                *(uint32_t*)&Ph[pb] = hw;
                *(uint32_t*)&Pl[pb] = lw;
                cvt_pair((acc[mt][nt][2] + b0) * scale,
                         (acc[mt][nt][3] + b1) * scale, hw, lw);
                *(uint32_t*)&Ph[pb + 64] = hw;
                *(uint32_t*)&Pl[pb + 64] = lw;
            }
        }
    }
}

// ===========================================================================
// Tensor-core flash attention (bf16 3-term, cp.async double-buffered K/V).
// ctx epilogue now writes fp16 hi/lo planes (exact split) for the O GEMM.
// ===========================================================================
#define ATTN_SMEM 163840

__global__ __launch_bounds__(256, 1) void attn_tc_kernel(
    const __nv_bfloat16* __restrict__ qh, const __nv_bfloat16* __restrict__ ql,
    const __nv_bfloat16* __restrict__ kh, const __nv_bfloat16* __restrict__ kl,
    const __nv_bfloat16* __restrict__ vh, const __nv_bfloat16* __restrict__ vl,
    __half* __restrict__ ch, __half* __restrict__ cl) {
    extern __shared__ char smem[];
    const uint32_t sb = smem_u32(smem);
    const int tid = threadIdx.x, wid = tid >> 5, lane = tid & 31;
    const int grp = lane >> 3, rin = lane & 7;
    const int head = blockIdx.y;
    const int q0 = blockIdx.x * 128;
    const size_t hbase = (size_t)head * 65536;

    enum { QH = 0, QL = 16384, STAGE0 = 32768, STAGE_SZ = 65536 };
    enum { KHo = 0, KLo = 16384, VHo = 32768, VLo = 49152 };

    {
        const uint4* sh = (const uint4*)(qh + hbase + (size_t)q0 * 64);
        const uint4* sl = (const uint4*)(ql + hbase + (size_t)q0 * 64);
        #pragma unroll
        for (int i = 0; i < 4; i++) {
            int c = tid + i * 256;
            uint32_t d = SW128(c * 16);
            uint4 a = sh[c]; sts128(sb + QH + d, a.x, a.y, a.z, a.w);
            uint4 b = sl[c]; sts128(sb + QL + d, b.x, b.y, b.z, b.w);
        }
    }

    auto issue_kv = [&](int kt) {
        const uint32_t st = sb + STAGE0 + (kt & 1) * STAGE_SZ;
        const size_t tb = hbase + (size_t)kt * 8192;
        const __nv_bfloat16* pkh = kh + tb;
        const __nv_bfloat16* pkl = kl + tb;
        const __nv_bfloat16* pvh = vh + tb;
        const __nv_bfloat16* pvl = vl + tb;
        #pragma unroll
        for (int i = 0; i < 4; i++) {
            int c = tid + i * 256;
            uint32_t d = SW128(c * 16);
            asm volatile("cp.async.cg.shared.global [%0], [%1], 16;" :: "r"(st + KHo + d), "l"(pkh + c * 8));
            asm volatile("cp.async.cg.shared.global [%0], [%1], 16;" :: "r"(st + KLo + d), "l"(pkl + c * 8));
            asm volatile("cp.async.cg.shared.global [%0], [%1], 16;" :: "r"(st + VHo + d), "l"(pvh + c * 8));
            asm volatile("cp.async.cg.shared.global [%0], [%1], 16;" :: "r"(st + VLo + d), "l"(pvl + c * 8));
        }
        asm volatile("cp.async.commit_group;" ::: "memory");
    };

    issue_kv(0);
    __syncthreads();

    const int a_row = wid * 16 + ((grp & 1) << 3) + rin;
    const int a_kb = (grp >> 1) << 4;
    uint32_t qfh[4][4], qfl[4][4];
    #pragma unroll
    for (int ks = 0; ks < 4; ks++) {
        uint32_t off = a_row * 128 + ks * 32 + a_kb;
        LDSM4(qfh[ks], sb + QH + SW128(off));
        LDSM4(qfl[ks], sb + QL + SW128(off));
    }

    const int b_rowb = ((grp >> 1) << 3) + rin;
    const int b_kb = (grp & 1) << 4;
    const int v_rowb = ((grp & 1) << 3) + rin;
    const int v_cb = (grp >> 1) << 4;

    float sc[16][4];
    float oacc[8][4];
    #pragma unroll
    for (int i = 0; i < 8; i++)
        #pragma unroll
        for (int j = 0; j < 4; j++) oacc[i][j] = 0.0f;
    float m1 = -INFINITY, m2 = -INFINITY, l1 = 0.0f, l2 = 0.0f;

    #pragma unroll 1
    for (int kt = 0; kt < 8; kt++) {
        __syncthreads();
        if (kt < 7) {
            issue_kv(kt + 1);
            asm volatile("cp.async.wait_group 1;" ::: "memory");
        } else {
            asm volatile("cp.async.wait_group 0;" ::: "memory");
        }
        __syncthreads();

        const uint32_t st = sb + STAGE0 + (kt & 1) * STAGE_SZ;

        #pragma unroll
        for (int j = 0; j < 16; j++)
            #pragma unroll
            for (int c = 0; c < 4; c++) sc[j][c] = 0.0f;
        #pragma unroll
        for (int ks = 0; ks < 4; ks++) {
            #pragma unroll
            for (int nb = 0; nb < 8; nb++) {
                uint32_t kfh[4], kfl[4];
                uint32_t off = (nb * 16 + b_rowb) * 128 + ks * 32 + b_kb;
                LDSM4(kfh, st + KHo + SW128(off));
                LDSM4(kfl, st + KLo + SW128(off));
                #pragma unroll
                for (int sub = 0; sub < 2; sub++)
                    MMA_BF16(sc[nb * 2 + sub], qfh[ks], kfh[sub * 2], kfh[sub * 2 + 1]);
                #pragma unroll
                for (int sub = 0; sub < 2; sub++)
                    MMA_BF16(sc[nb * 2 + sub], qfl[ks], kfh[sub * 2], kfh[sub * 2 + 1]);
                #pragma unroll
                for (int sub = 0; sub < 2; sub++)
                    MMA_BF16(sc[nb * 2 + sub], qfh[ks], kfl[sub * 2], kfl[sub * 2 + 1]);
            }
        }

        float tm1 = -INFINITY, tm2 = -INFINITY;
        #pragma unroll
        for (int j = 0; j < 16; j++) {
            tm1 = fmaxf(tm1, fmaxf(sc[j][0], sc[j][1]));
            tm2 = fmaxf(tm2, fmaxf(sc[j][2], sc[j][3]));
        }
        tm1 = fmaxf(tm1, __shfl_xor_sync(0xffffffffu, tm1, 1));
        tm1 = fmaxf(tm1, __shfl_xor_sync(0xffffffffu, tm1, 2));
        tm2 = fmaxf(tm2, __shfl_xor_sync(0xffffffffu, tm2, 1));
        tm2 = fmaxf(tm2, __shfl_xor_sync(0xffffffffu, tm2, 2));

        float mn1 = fmaxf(m1, tm1), mn2 = fmaxf(m2, tm2);
        float al1 = __expf(m1 - mn1), al2 = __expf(m2 - mn2);
        m1 = mn1; m2 = mn2;

        float s1 = 0.0f, s2 = 0.0f;
        #pragma unroll
        for (int j = 0; j < 16; j++) {
            sc[j][0] = __expf(sc[j][0] - mn1);
            sc[j][1] = __expf(sc[j][1] - mn1);
            s1 += sc[j][0] + sc[j][1];
            sc[j][2] = __expf(sc[j][2] - mn2);
            sc[j][3] = __expf(sc[j][3] - mn2);
            s2 += sc[j][2] + sc[j][3];
        }
        s1 += __shfl_xor_sync(0xffffffffu, s1, 1);
        s1 += __shfl_xor_sync(0xffffffffu, s1, 2);
        s2 += __shfl_xor_sync(0xffffffffu, s2, 1);
        s2 += __shfl_xor_sync(0xffffffffu, s2, 2);
        l1 = l1 * al1 + s1;
        l2 = l2 * al2 + s2;
        #pragma unroll
        for (int nb = 0; nb < 8; nb++) {
            oacc[nb][0] *= al1; oacc[nb][1] *= al1;
            oacc[nb][2] *= al2; oacc[nb][3] *= al2;
        }

        #pragma unroll
        for (int ksv = 0; ksv < 8; ksv++) {
            uint32_t pah[4], pal[4];
            const int j0 = 2 * ksv, j1 = j0 + 1;
            cvt_pair(sc[j0][0], sc[j0][1], pah[0], pal[0]);
            cvt_pair(sc[j0][2], sc[j0][3], pah[1], pal[1]);
            cvt_pair(sc[j1][0], sc[j1][1], pah[2], pal[2]);
            cvt_pair(sc[j1][2], sc[j1][3], pah[3], pal[3]);
            #pragma unroll
            for (int nv = 0; nv < 4; nv++) {
                uint32_t vfh[4], vfl[4];
                uint32_t off = (ksv * 16 + v_rowb) * 128 + nv * 32 + v_cb;
                LDSM4T(vfh, st + VHo + SW128(off));
                LDSM4T(vfl, st + VLo + SW128(off));
                #pragma unroll
                for (int sub = 0; sub < 2; sub++)
                    MMA_BF16(oacc[nv * 2 + sub], pah, vfh[sub * 2], vfh[sub * 2 + 1]);
                #pragma unroll
                for (int sub = 0; sub < 2; sub++)
                    MMA_BF16(oacc[nv * 2 + sub], pal, vfh[sub * 2], vfh[sub * 2 + 1]);
                #pragma unroll
                for (int sub = 0; sub < 2; sub++)
                    MMA_BF16(oacc[nv * 2 + sub], pah, vfl[sub * 2], vfl[sub * 2 + 1]);
            }
        }
    }

    // normalize + write ctx fp16 hi/lo planes [t*8+b][1024]
    const float inv1 = 1.0f / l1, inv2 = 1.0f / l2;
    const int t1 = q0 + wid * 16 + (lane >> 2);
    const int bb = head >> 4, hh = head & 15;
    const int colb = hh * 64 + 2 * (lane & 3);
    #pragma unroll
    for (int nb = 0; nb < 8; nb++) {
        int col = colb + nb * 8;
        size_t o1 = ((size_t)t1 * 8 + bb) * 1024 + col;
        uint32_t hw, lw;
        cvt_pair_h(oacc[nb][0] * inv1, oacc[nb][1] * inv1, hw, lw);
        *(uint32_t*)&ch[o1] = hw;
        *(uint32_t*)&cl[o1] = lw;
        cvt_pair_h(oacc[nb][2] * inv2, oacc[nb][3] * inv2, hw, lw);
        *(uint32_t*)&ch[o1 + 65536] = hw;
        *(uint32_t*)&cl[o1 + 65536] = lw;
    }
}

// ===========================================================================
// Launch
// ===========================================================================
extern "C" void kernel_launch(void* const* d_in, const int* in_sizes, int n_in,
                              void* d_out, int out_size) {
    const float* query = (const float*)d_in[0];
    const float* key   = (const float*)d_in[1];
    const float* value = (const float*)d_in[2];
    const float* Wq = (const float*)d_in[3];
    const float* bq = (const float*)d_in[4];
    const float* Wk = (const float*)d_in[5];
    const float* bk = (const float*)d_in[6];
    const float* Wv = (const float*)d_in[7];
    const float* bv = (const float*)d_in[8];
    const float* Wo = (const float*)d_in[9];
    const float* bo = (const float*)d_in[10];
    float* out = (float*)d_out;

    __nv_bfloat16 *pqh, *pql, *pkh, *pkl, *pvh, *pvl;
    __half *xh, *xl, *wh, *ch, *cl;
    float* biasb;
    cudaGetSymbolAddress((void**)&pqh, g_qh);
    cudaGetSymbolAddress((void**)&pql, g_ql);
    cudaGetSymbolAddress((void**)&pkh, g_kh);
    cudaGetSymbolAddress((void**)&pkl, g_kl);
    cudaGetSymbolAddress((void**)&pvh, g_vh);
    cudaGetSymbolAddress((void**)&pvl, g_vl);
    cudaGetSymbolAddress((void**)&xh, g_xh);
    cudaGetSymbolAddress((void**)&xl, g_xl);
    cudaGetSymbolAddress((void**)&wh, g_wh);
    cudaGetSymbolAddress((void**)&ch, g_ch);
    cudaGetSymbolAddress((void**)&cl, g_cl);
    cudaGetSymbolAddress((void**)&biasb, g_bias);

    cudaFuncSetAttribute(gemm_tc_kernel,
                         cudaFuncAttributeMaxDynamicSharedMemorySize, GEMM_SMEM);
    cudaFuncSetAttribute(attn_tc_kernel,
                         cudaFuncAttributeMaxDynamicSharedMemorySize, ATTN_SMEM);

    const int n4_in = M_ROWS * D_DIM / 4;
    const int n4_w  = D_DIM * D_DIM / 4;
    const int W_OFF  = D_DIM * D_DIM;

    cvt3_kernel<<<dim3(1024, 3), 256>>>(query, key, value, xh, xl, n4_in);
    cvtw_kernel<<<dim3(256, 4), 256>>>(Wq, Wk, Wv, Wo, wh, n4_w);
    cudaMemcpyAsync(biasb, bq, D_DIM * sizeof(float), cudaMemcpyDeviceToDevice);
    cudaMemcpyAsync(biasb + D_DIM, bk, D_DIM * sizeof(float), cudaMemcpyDeviceToDevice);
    cudaMemcpyAsync(biasb + 2 * D_DIM, bv, D_DIM * sizeof(float), cudaMemcpyDeviceToDevice);

    dim3 qkv_grid(D_DIM / 128, 3 * M_ROWS / 128);
    gemm_tc_kernel<<<qkv_grid, 256, GEMM_SMEM>>>(xh, xl, wh, biasb, nullptr,
                                                 pqh, pql, pkh, pkl, pvh, pvl);

    dim3 attn_grid(T_DIM / 128, B_DIM * H_DIM);
    attn_tc_kernel<<<attn_grid, 256, ATTN_SMEM>>>(pqh, pql, pkh, pkl,
                                                  pvh, pvl, ch, cl);

    dim3 o_grid(D_DIM / 128, M_ROWS / 128);
    gemm_tc_kernel<<<o_grid, 256, GEMM_SMEM>>>(ch, cl, wh + 3 * W_OFF,
                                               bo, out,
                                               pqh, pql, pkh, pkl, pvh, pvl);
}

// round 17
// speedup vs baseline: 1.6137x; 1.1401x over previous
#include <cuda_runtime.h>
#include <cuda_bf16.h>
#include <cuda_fp16.h>
#include <stdint.h>
#include <math.h>

// Problem constants
#define T_DIM 1024
#define B_DIM 8
#define D_DIM 1024
#define H_DIM 16
#define HD_DIM 64
#define M_ROWS (T_DIM * B_DIM)        // 8192

// Scratch (no cudaMalloc allowed)
#define PLANE_ELEMS (128 * 1024 * 64)
__device__ __half g_qh[PLANE_ELEMS], g_ql[PLANE_ELEMS];   // Q fp16 hi/lo head planes
__device__ __half g_kp[PLANE_ELEMS];                      // K single fp16 plane
__device__ __half g_vp[PLANE_ELEMS];                      // V single fp16 plane
__device__ __half g_xh[3 * M_ROWS * D_DIM], g_xl[3 * M_ROWS * D_DIM];  // fp16 input planes
__device__ __half g_wh[4 * D_DIM * D_DIM];                             // fp16 weights (rounded)
__device__ __half g_ch[M_ROWS * D_DIM], g_cl[M_ROWS * D_DIM];          // fp16 ctx planes
__device__ float g_bias[3 * D_DIM];

// ===========================================================================
// Helpers
// ===========================================================================
__device__ __forceinline__ uint32_t smem_u32(const void* p) {
    uint32_t a;
    asm("{ .reg .u64 t; cvta.to.shared.u64 t, %1; cvt.u32.u64 %0, t; }"
        : "=r"(a) : "l"(p));
    return a;
}
#define SW128(o) ((o) ^ (((o) >> 3) & 0x70))

#define LDSM4(r, addr) \
    asm volatile("ldmatrix.sync.aligned.m8n8.x4.shared.b16 {%0,%1,%2,%3}, [%4];" \
        : "=r"((r)[0]), "=r"((r)[1]), "=r"((r)[2]), "=r"((r)[3]) : "r"(addr))

#define LDSM4T(r, addr) \
    asm volatile("ldmatrix.sync.aligned.m8n8.x4.trans.shared.b16 {%0,%1,%2,%3}, [%4];" \
        : "=r"((r)[0]), "=r"((r)[1]), "=r"((r)[2]), "=r"((r)[3]) : "r"(addr))

#define MMA_FP16(d, a, b0_, b1_) \
    asm volatile("mma.sync.aligned.m16n8k16.row.col.f32.f16.f16.f32 " \
        "{%0,%1,%2,%3}, {%4,%5,%6,%7}, {%8,%9}, {%0,%1,%2,%3};" \
        : "+f"((d)[0]), "+f"((d)[1]), "+f"((d)[2]), "+f"((d)[3]) \
        : "r"((a)[0]), "r"((a)[1]), "r"((a)[2]), "r"((a)[3]), \
          "r"(b0_), "r"(b1_))

__device__ __forceinline__ void sts128(uint32_t addr, uint32_t a, uint32_t b,
                                       uint32_t c, uint32_t d) {
    asm volatile("st.shared.v4.b32 [%0], {%1,%2,%3,%4};"
                 :: "r"(addr), "r"(a), "r"(b), "r"(c), "r"(d) : "memory");
}
// split fp32 pair -> (hi fp16x2, lo fp16x2)
__device__ __forceinline__ void cvt_pair_h(float f0, float f1,
                                           uint32_t& hw, uint32_t& lw) {
    __half2 h = __floats2half2_rn(f0, f1);
    float g0 = __half2float(__low2half(h));
    float g1 = __half2float(__high2half(h));
    __half2 l = __floats2half2_rn(f0 - g0, f1 - g1);
    hw = *reinterpret_cast<uint32_t*>(&h);
    lw = *reinterpret_cast<uint32_t*>(&l);
}
__device__ __forceinline__ uint32_t pack_h2(float f0, float f1) {
    __half2 h = __floats2half2_rn(f0, f1);
    return *reinterpret_cast<uint32_t*>(&h);
}

// ===========================================================================
// Preconvert: inputs -> fp16 hi/lo planes; weights -> single rounded fp16
// ===========================================================================
__global__ __launch_bounds__(256) void cvt3_kernel(
    const float* __restrict__ s0, const float* __restrict__ s1,
    const float* __restrict__ s2,
    __half* __restrict__ h, __half* __restrict__ l, int n4seg) {
    const int segi = blockIdx.y;
    const float* s = (segi == 0) ? s0 : (segi == 1 ? s1 : s2);
    const int base = segi * n4seg;
    const int stride = gridDim.x * 256;
    for (int j = blockIdx.x * 256 + threadIdx.x; j < n4seg; j += stride) {
        float4 v = ((const float4*)s)[j];
        uint32_t h0, h1, l0, l1;
        cvt_pair_h(v.x, v.y, h0, l0);
        cvt_pair_h(v.z, v.w, h1, l1);
        ((uint2*)h)[base + j] = make_uint2(h0, h1);
        ((uint2*)l)[base + j] = make_uint2(l0, l1);
    }
}

__global__ __launch_bounds__(256) void cvtw_kernel(
    const float* __restrict__ s0, const float* __restrict__ s1,
    const float* __restrict__ s2, const float* __restrict__ s3,
    __half* __restrict__ w, int n4seg) {
    const int segi = blockIdx.y;
    const float* s = (segi == 0) ? s0 : (segi == 1 ? s1 : (segi == 2 ? s2 : s3));
    const int base = segi * n4seg;
    const int stride = gridDim.x * 256;
    for (int j = blockIdx.x * 256 + threadIdx.x; j < n4seg; j += stride) {
        float4 v = ((const float4*)s)[j];
        ((uint2*)w)[base + j] = make_uint2(pack_h2(v.x, v.y), pack_h2(v.z, v.w));
    }
}

// ===========================================================================
// fp16 2-term warp-MMA GEMM: out = X @ W^T + bias.
// Epilogues: fp32 C (C!=nullptr), else head planes:
//   seg0 -> Q fp16 hi/lo (scaled 0.125), seg1 -> K single fp16,
//   seg2 -> V single fp16.
// ===========================================================================
#define NSTAGE 3
#define G_STAGE 32768
#define GEMM_SMEM (NSTAGE * G_STAGE)   // 98304

__global__ __launch_bounds__(256, 2) void gemm_tc_kernel(
    const __half* __restrict__ Ah_, const __half* __restrict__ Al_,
    const __half* __restrict__ Wh_,
    const float* __restrict__ bias, float* __restrict__ C,
    __half* __restrict__ qh, __half* __restrict__ ql,
    __half* __restrict__ kp, __half* __restrict__ vp) {
    extern __shared__ char smem[];
    const uint32_t sb = smem_u32(smem);

    const int tid = threadIdx.x;
    const int wid = tid >> 5;
    const int lane = tid & 31;
    const int wm = wid >> 2;
    const int wn = wid & 3;
    const int seg = blockIdx.y >> 6;
    const int row0 = blockIdx.y * 128;
    const int wrow0 = seg * 1024 + blockIdx.x * 128;
    const int col0 = blockIdx.x * 128;

    const int grp = lane >> 3, rin = lane & 7;
    const int a_mrow = ((grp & 1) << 3) + rin;
    const int a_kb   = (grp >> 1) << 4;
    const int b_nrow = ((grp >> 1) << 3) + rin;
    const int b_kb   = (grp & 1) << 4;

    const int rbase = tid >> 2;
    const int cseg = tid & 3;
    const size_t offA0 = (size_t)(row0 + rbase) * 1024 + cseg * 8;
    const size_t offA1 = offA0 + (size_t)64 * 1024;
    const size_t offW0 = (size_t)(wrow0 + rbase) * 1024 + cseg * 8;
    const size_t offW1 = offW0 + (size_t)64 * 1024;
    const uint32_t s0 = SW128(rbase * 128 + cseg * 16);
    const uint32_t s1 = SW128((64 + rbase) * 128 + cseg * 16);
    const uint32_t s2 = SW128(rbase * 128 + 64 + cseg * 16);
    const uint32_t s3 = SW128((64 + rbase) * 128 + 64 + cseg * 16);

    auto issue_stage = [&](int s) {
        const int kb = s * 32;
        const uint32_t dst = sb + (s % NSTAGE) * G_STAGE;
        asm volatile("cp.async.cg.shared.global [%0], [%1], 16;" :: "r"(dst + s0), "l"(Ah_ + offA0 + kb));
        asm volatile("cp.async.cg.shared.global [%0], [%1], 16;" :: "r"(dst + s1), "l"(Ah_ + offA1 + kb));
        asm volatile("cp.async.cg.shared.global [%0], [%1], 16;" :: "r"(dst + s2), "l"(Al_ + offA0 + kb));
        asm volatile("cp.async.cg.shared.global [%0], [%1], 16;" :: "r"(dst + s3), "l"(Al_ + offA1 + kb));
        asm volatile("cp.async.cg.shared.global [%0], [%1], 16;" :: "r"(dst + 16384 + s0), "l"(Wh_ + offW0 + kb));
        asm volatile("cp.async.cg.shared.global [%0], [%1], 16;" :: "r"(dst + 16384 + s1), "l"(Wh_ + offW1 + kb));
        asm volatile("cp.async.commit_group;" ::: "memory");
    };

    float acc[4][4][4];
    #pragma unroll
    for (int i = 0; i < 4; i++)
        #pragma unroll
        for (int j = 0; j < 4; j++)
            #pragma unroll
            for (int k = 0; k < 4; k++) acc[i][j][k] = 0.0f;

    issue_stage(0);
    issue_stage(1);

    #pragma unroll 1
    for (int s = 0; s < 32; s++) {
        asm volatile("cp.async.wait_group %0;" :: "n"(NSTAGE - 2) : "memory");
        __syncthreads();
        if (s + 2 < 32) issue_stage(s + 2);
        else asm volatile("cp.async.commit_group;" ::: "memory");

        const uint32_t AsB = sb + (s % NSTAGE) * G_STAGE;
        const uint32_t BsB = AsB + 16384;
        #pragma unroll
        for (int ks = 0; ks < 2; ks++) {
            uint32_t ah[4][4], al[4][4], bh[2][4];
            #pragma unroll
            for (int mt = 0; mt < 4; mt++) {
                int row = wm * 64 + mt * 16 + a_mrow;
                uint32_t off = row * 128 + ks * 32 + a_kb;
                LDSM4(ah[mt], AsB + SW128(off));
                LDSM4(al[mt], AsB + SW128(off + 64));
            }
            #pragma unroll
            for (int np = 0; np < 2; np++) {
                int row = wn * 32 + np * 16 + b_nrow;
                uint32_t off = row * 128 + ks * 32 + b_kb;
                LDSM4(bh[np], BsB + SW128(off));
            }
            #pragma unroll
            for (int mt = 0; mt < 4; mt++)
                #pragma unroll
                for (int np = 0; np < 2; np++)
                    #pragma unroll
                    for (int sub = 0; sub < 2; sub++)
                        MMA_FP16(acc[mt][np * 2 + sub], ah[mt],
                                 bh[np][sub * 2], bh[np][sub * 2 + 1]);
            #pragma unroll
            for (int mt = 0; mt < 4; mt++)
                #pragma unroll
                for (int np = 0; np < 2; np++)
                    #pragma unroll
                    for (int sub = 0; sub < 2; sub++)
                        MMA_FP16(acc[mt][np * 2 + sub], al[mt],
                                 bh[np][sub * 2], bh[np][sub * 2 + 1]);
        }
    }

    if (C != nullptr) {
        #pragma unroll
        for (int mt = 0; mt < 4; mt++) {
            int rg = row0 + wm * 64 + mt * 16 + (lane >> 2);
            #pragma unroll
            for (int nt = 0; nt < 4; nt++) {
                int cg = col0 + wn * 32 + nt * 8 + (lane & 3) * 2;
                float b0 = __ldg(&bias[cg]), b1 = __ldg(&bias[cg + 1]);
                float2 v0 = make_float2(acc[mt][nt][0] + b0, acc[mt][nt][1] + b1);
                float2 v1 = make_float2(acc[mt][nt][2] + b0, acc[mt][nt][3] + b1);
                *(float2*)&C[(size_t)rg * 1024 + cg] = v0;
                *(float2*)&C[(size_t)(rg + 8) * 1024 + cg] = v1;
            }
        }
    } else if (seg == 0) {
        // Q: fp16 hi/lo planes, scaled 1/8
        const int ry = (blockIdx.y & 63) * 128;
        #pragma unroll
        for (int mt = 0; mt < 4; mt++) {
            int rg = ry + wm * 64 + mt * 16 + (lane >> 2);
            int t = rg >> 3, bb = rg & 7;
            #pragma unroll
            for (int nt = 0; nt < 4; nt++) {
                int cg = col0 + wn * 32 + nt * 8 + (lane & 3) * 2;
                int hh = cg >> 6, hd = cg & 63;
                size_t pb = ((size_t)(bb * 16 + hh)) * 65536 + (size_t)t * 64 + hd;
                float b0 = __ldg(&bias[cg]), b1 = __ldg(&bias[cg + 1]);
                uint32_t hw, lw;
                cvt_pair_h((acc[mt][nt][0] + b0) * 0.125f,
                           (acc[mt][nt][1] + b1) * 0.125f, hw, lw);
                *(uint32_t*)&qh[pb] = hw;
                *(uint32_t*)&ql[pb] = lw;
                cvt_pair_h((acc[mt][nt][2] + b0) * 0.125f,
                           (acc[mt][nt][3] + b1) * 0.125f, hw, lw);
                *(uint32_t*)&qh[pb + 64] = hw;
                *(uint32_t*)&ql[pb + 64] = lw;
            }
        }
    } else {
        // K or V: single fp16 plane
        __half* P = (seg == 1) ? kp : vp;
        const int ry = (blockIdx.y & 63) * 128;
        #pragma unroll
        for (int mt = 0; mt < 4; mt++) {
            int rg = ry + wm * 64 + mt * 16 + (lane >> 2);
            int t = rg >> 3, bb = rg & 7;
            #pragma unroll
            for (int nt = 0; nt < 4; nt++) {
                int cg = col0 + wn * 32 + nt * 8 + (lane & 3) * 2;
                int hh = cg >> 6, hd = cg & 63;
                size_t pb = ((size_t)(bb * 16 + hh)) * 65536 + (size_t)t * 64 + hd;
                float b0 = __ldg(&bias[seg * 1024 + cg]);
                float b1 = __ldg(&bias[seg * 1024 + cg + 1]);
                *(uint32_t*)&P[pb] = pack_h2(acc[mt][nt][0] + b0, acc[mt][nt][1] + b1);
                *(uint32_t*)&P[pb + 64] = pack_h2(acc[mt][nt][2] + b0, acc[mt][nt][3] + b1);
            }
        }
    }
}

// ===========================================================================
// Tensor-core flash attention, fp16 2-term on both matmuls:
//   S = (Qh + Ql) Kp^T ;  O = (Ph + Pl) Vp   (K, V single fp16 planes)
// cp.async double-buffered K/V (32 KB/stage). SMEM: QH 0 | QL 16K |
// stage0 {K,V} @32K | stage1 @64K = 96 KB
// ===========================================================================
#define ATTN_SMEM 98304

__global__ __launch_bounds__(256, 1) void attn_tc_kernel(
    const __half* __restrict__ qh, const __half* __restrict__ ql,
    const __half* __restrict__ kp, const __half* __restrict__ vp,
    __half* __restrict__ ch, __half* __restrict__ cl) {
    extern __shared__ char smem[];
    const uint32_t sb = smem_u32(smem);
    const int tid = threadIdx.x, wid = tid >> 5, lane = tid & 31;
    const int grp = lane >> 3, rin = lane & 7;
    const int head = blockIdx.y;
    const int q0 = blockIdx.x * 128;
    const size_t hbase = (size_t)head * 65536;

    enum { QH = 0, QL = 16384, STAGE0 = 32768, STAGE_SZ = 32768 };
    enum { KHo = 0, VHo = 16384 };

    {
        const uint4* sh = (const uint4*)(qh + hbase + (size_t)q0 * 64);
        const uint4* sl = (const uint4*)(ql + hbase + (size_t)q0 * 64);
        #pragma unroll
        for (int i = 0; i < 4; i++) {
            int c = tid + i * 256;
            uint32_t d = SW128(c * 16);
            uint4 a = sh[c]; sts128(sb + QH + d, a.x, a.y, a.z, a.w);
            uint4 b = sl[c]; sts128(sb + QL + d, b.x, b.y, b.z, b.w);
        }
    }

    auto issue_kv = [&](int kt) {
        const uint32_t st = sb + STAGE0 + (kt & 1) * STAGE_SZ;
        const size_t tb = hbase + (size_t)kt * 8192;
        const __half* pk = kp + tb;
        const __half* pv = vp + tb;
        #pragma unroll
        for (int i = 0; i < 4; i++) {
            int c = tid + i * 256;
            uint32_t d = SW128(c * 16);
            asm volatile("cp.async.cg.shared.global [%0], [%1], 16;" :: "r"(st + KHo + d), "l"(pk + c * 8));
            asm volatile("cp.async.cg.shared.global [%0], [%1], 16;" :: "r"(st + VHo + d), "l"(pv + c * 8));
        }
        asm volatile("cp.async.commit_group;" ::: "memory");
    };

    issue_kv(0);
    __syncthreads();

    const int a_row = wid * 16 + ((grp & 1) << 3) + rin;
    const int a_kb = (grp >> 1) << 4;
    uint32_t qfh[4][4], qfl[4][4];
    #pragma unroll
    for (int ks = 0; ks < 4; ks++) {
        uint32_t off = a_row * 128 + ks * 32 + a_kb;
        LDSM4(qfh[ks], sb + QH + SW128(off));
        LDSM4(qfl[ks], sb + QL + SW128(off));
    }

    const int b_rowb = ((grp >> 1) << 3) + rin;
    const int b_kb = (grp & 1) << 4;
    const int v_rowb = ((grp & 1) << 3) + rin;
    const int v_cb = (grp >> 1) << 4;

    float sc[16][4];
    float oacc[8][4];
    #pragma unroll
    for (int i = 0; i < 8; i++)
        #pragma unroll
        for (int j = 0; j < 4; j++) oacc[i][j] = 0.0f;
    float m1 = -INFINITY, m2 = -INFINITY, l1 = 0.0f, l2 = 0.0f;

    #pragma unroll 1
    for (int kt = 0; kt < 8; kt++) {
        __syncthreads();
        if (kt < 7) {
            issue_kv(kt + 1);
            asm volatile("cp.async.wait_group 1;" ::: "memory");
        } else {
            asm volatile("cp.async.wait_group 0;" ::: "memory");
        }
        __syncthreads();

        const uint32_t st = sb + STAGE0 + (kt & 1) * STAGE_SZ;

        // ---- S = Q K^T (2 fp16 terms) ----
        #pragma unroll
        for (int j = 0; j < 16; j++)
            #pragma unroll
            for (int c = 0; c < 4; c++) sc[j][c] = 0.0f;
        #pragma unroll
        for (int ks = 0; ks < 4; ks++) {
            #pragma unroll
            for (int nb = 0; nb < 8; nb++) {
                uint32_t kf[4];
                uint32_t off = (nb * 16 + b_rowb) * 128 + ks * 32 + b_kb;
                LDSM4(kf, st + KHo + SW128(off));
                #pragma unroll
                for (int sub = 0; sub < 2; sub++)
                    MMA_FP16(sc[nb * 2 + sub], qfh[ks], kf[sub * 2], kf[sub * 2 + 1]);
                #pragma unroll
                for (int sub = 0; sub < 2; sub++)
                    MMA_FP16(sc[nb * 2 + sub], qfl[ks], kf[sub * 2], kf[sub * 2 + 1]);
            }
        }

        // ---- online softmax ----
        float tm1 = -INFINITY, tm2 = -INFINITY;
        #pragma unroll
        for (int j = 0; j < 16; j++) {
            tm1 = fmaxf(tm1, fmaxf(sc[j][0], sc[j][1]));
            tm2 = fmaxf(tm2, fmaxf(sc[j][2], sc[j][3]));
        }
        tm1 = fmaxf(tm1, __shfl_xor_sync(0xffffffffu, tm1, 1));
        tm1 = fmaxf(tm1, __shfl_xor_sync(0xffffffffu, tm1, 2));
        tm2 = fmaxf(tm2, __shfl_xor_sync(0xffffffffu, tm2, 1));
        tm2 = fmaxf(tm2, __shfl_xor_sync(0xffffffffu, tm2, 2));

        float mn1 = fmaxf(m1, tm1), mn2 = fmaxf(m2, tm2);
        float al1 = __expf(m1 - mn1), al2 = __expf(m2 - mn2);
        m1 = mn1; m2 = mn2;

        float s1 = 0.0f, s2 = 0.0f;
        #pragma unroll
        for (int j = 0; j < 16; j++) {
            sc[j][0] = __expf(sc[j][0] - mn1);
            sc[j][1] = __expf(sc[j][1] - mn1);
            s1 += sc[j][0] + sc[j][1];
            sc[j][2] = __expf(sc[j][2] - mn2);
            sc[j][3] = __expf(sc[j][3] - mn2);
            s2 += sc[j][2] + sc[j][3];
        }
        s1 += __shfl_xor_sync(0xffffffffu, s1, 1);
        s1 += __shfl_xor_sync(0xffffffffu, s1, 2);
        s2 += __shfl_xor_sync(0xffffffffu, s2, 1);
        s2 += __shfl_xor_sync(0xffffffffu, s2, 2);
        l1 = l1 * al1 + s1;
        l2 = l2 * al2 + s2;
        #pragma unroll
        for (int nb = 0; nb < 8; nb++) {
            oacc[nb][0] *= al1; oacc[nb][1] *= al1;
            oacc[nb][2] *= al2; oacc[nb][3] *= al2;
        }

        // ---- O += P V (2 fp16 terms; P split exact) ----
        #pragma unroll
        for (int ksv = 0; ksv < 8; ksv++) {
            uint32_t pah[4], pal[4];
            const int j0 = 2 * ksv, j1 = j0 + 1;
            cvt_pair_h(sc[j0][0], sc[j0][1], pah[0], pal[0]);
            cvt_pair_h(sc[j0][2], sc[j0][3], pah[1], pal[1]);
            cvt_pair_h(sc[j1][0], sc[j1][1], pah[2], pal[2]);
            cvt_pair_h(sc[j1][2], sc[j1][3], pah[3], pal[3]);
            #pragma unroll
            for (int nv = 0; nv < 4; nv++) {
                uint32_t vf[4];
                uint32_t off = (ksv * 16 + v_rowb) * 128 + nv * 32 + v_cb;
                LDSM4T(vf, st + VHo + SW128(off));
                #pragma unroll
                for (int sub = 0; sub < 2; sub++)
                    MMA_FP16(oacc[nv * 2 + sub], pah, vf[sub * 2], vf[sub * 2 + 1]);
                #pragma unroll
                for (int sub = 0; sub < 2; sub++)
                    MMA_FP16(oacc[nv * 2 + sub], pal, vf[sub * 2], vf[sub * 2 + 1]);
            }
        }
    }

    // normalize + write ctx fp16 hi/lo planes [t*8+b][1024]
    const float inv1 = 1.0f / l1, inv2 = 1.0f / l2;
    const int t1 = q0 + wid * 16 + (lane >> 2);
    const int bb = head >> 4, hh = head & 15;
    const int colb = hh * 64 + 2 * (lane & 3);
    #pragma unroll
    for (int nb = 0; nb < 8; nb++) {
        int col = colb + nb * 8;
        size_t o1 = ((size_t)t1 * 8 + bb) * 1024 + col;
        uint32_t hw, lw;
        cvt_pair_h(oacc[nb][0] * inv1, oacc[nb][1] * inv1, hw, lw);
        *(uint32_t*)&ch[o1] = hw;
        *(uint32_t*)&cl[o1] = lw;
        cvt_pair_h(oacc[nb][2] * inv2, oacc[nb][3] * inv2, hw, lw);
        *(uint32_t*)&ch[o1 + 65536] = hw;
        *(uint32_t*)&cl[o1 + 65536] = lw;
    }
}

// ===========================================================================
// Launch
// ===========================================================================
extern "C" void kernel_launch(void* const* d_in, const int* in_sizes, int n_in,
                              void* d_out, int out_size) {
    const float* query = (const float*)d_in[0];
    const float* key   = (const float*)d_in[1];
    const float* value = (const float*)d_in[2];
    const float* Wq = (const float*)d_in[3];
    const float* bq = (const float*)d_in[4];
    const float* Wk = (const float*)d_in[5];
    const float* bk = (const float*)d_in[6];
    const float* Wv = (const float*)d_in[7];
    const float* bv = (const float*)d_in[8];
    const float* Wo = (const float*)d_in[9];
    const float* bo = (const float*)d_in[10];
    float* out = (float*)d_out;

    __half *pqh, *pql, *pkp, *pvp, *xh, *xl, *wh, *ch, *cl;
    float* biasb;
    cudaGetSymbolAddress((void**)&pqh, g_qh);
    cudaGetSymbolAddress((void**)&pql, g_ql);
    cudaGetSymbolAddress((void**)&pkp, g_kp);
    cudaGetSymbolAddress((void**)&pvp, g_vp);
    cudaGetSymbolAddress((void**)&xh, g_xh);
    cudaGetSymbolAddress((void**)&xl, g_xl);
    cudaGetSymbolAddress((void**)&wh, g_wh);
    cudaGetSymbolAddress((void**)&ch, g_ch);
    cudaGetSymbolAddress((void**)&cl, g_cl);
    cudaGetSymbolAddress((void**)&biasb, g_bias);

    cudaFuncSetAttribute(gemm_tc_kernel,
                         cudaFuncAttributeMaxDynamicSharedMemorySize, GEMM_SMEM);
    cudaFuncSetAttribute(attn_tc_kernel,
                         cudaFuncAttributeMaxDynamicSharedMemorySize, ATTN_SMEM);

    const int n4_in = M_ROWS * D_DIM / 4;
    const int n4_w  = D_DIM * D_DIM / 4;
    const int W_OFF  = D_DIM * D_DIM;

    cvt3_kernel<<<dim3(1024, 3), 256>>>(query, key, value, xh, xl, n4_in);
    cvtw_kernel<<<dim3(256, 4), 256>>>(Wq, Wk, Wv, Wo, wh, n4_w);
    cudaMemcpyAsync(biasb, bq, D_DIM * sizeof(float), cudaMemcpyDeviceToDevice);
    cudaMemcpyAsync(biasb + D_DIM, bk, D_DIM * sizeof(float), cudaMemcpyDeviceToDevice);
    cudaMemcpyAsync(biasb + 2 * D_DIM, bv, D_DIM * sizeof(float), cudaMemcpyDeviceToDevice);

    dim3 qkv_grid(D_DIM / 128, 3 * M_ROWS / 128);
    gemm_tc_kernel<<<qkv_grid, 256, GEMM_SMEM>>>(xh, xl, wh, biasb, nullptr,
                                                 pqh, pql, pkp, pvp);

    dim3 attn_grid(T_DIM / 128, B_DIM * H_DIM);
    attn_tc_kernel<<<attn_grid, 256, ATTN_SMEM>>>(pqh, pql, pkp, pvp, ch, cl);

    dim3 o_grid(D_DIM / 128, M_ROWS / 128);
    gemm_tc_kernel<<<o_grid, 256, GEMM_SMEM>>>(ch, cl, wh + 3 * W_OFF,
                                               bo, out,
                                               pqh, pql, pkp, pvp);
}